// round 7
// baseline (speedup 1.0000x reference)
#include <cuda_runtime.h>
#include <cuda_bf16.h>
#include <cstdint>

#define NN     20000
#define NEIGH  12
#define EE     (NN*NEIGH)
#define HD     64
#define INB    480
#define INA    2880
#define NCRYS  20

// ---------------- scratch ----------------------------------------------------
__device__ __align__(256) char g_Wq0[256 * INA];   // weight digit b0
__device__ __align__(256) char g_Wq1[256 * INA];   // weight digit 2*b1
__device__ __align__(256) __nv_bfloat16 g_Wth[256 * HD];
__device__ __align__(256) __nv_bfloat16 g_Wtl[256 * HD];
__device__ float g_wmax[2];
__device__ float g_H[(size_t)NN * 256];
__device__ float g_bf[NN * HD];
__device__ float g_af[NN * HD];
__device__ __align__(256) __nv_bfloat16 g_bfh[NN * HD], g_bfl[NN * HD];
__device__ __align__(256) __nv_bfloat16 g_afh[NN * HD], g_afl[NN * HD];
__device__ int   g_cnt[NN * 3];
__device__ int   g_deg[NN];
__device__ int   g_off[NN + 1];
__device__ int   g_pos[NN];
__device__ int   g_rev[EE];
__device__ float g_pool[NCRYS * 128];

// ---------------- helpers ------------------------------------------------------
__device__ __forceinline__ uint32_t smem_u32(const void* p) {
    uint32_t a;
    asm("{ .reg .u64 t; cvta.to.shared.u64 t, %1; cvt.u32.u64 %0, t; }"
        : "=r"(a) : "l"(p));
    return a;
}

__device__ __forceinline__ void cp16(uint32_t dst, const void* src, int sz) {
    asm volatile("cp.async.cg.shared.global [%0], [%1], 16, %2;"
                 :: "r"(dst), "l"(src), "r"(sz));
}

__device__ __forceinline__ void ldmx4(uint32_t* r, uint32_t addr) {
    asm volatile("ldmatrix.sync.aligned.m8n8.x4.shared.b16 {%0,%1,%2,%3}, [%4];"
                 : "=r"(r[0]), "=r"(r[1]), "=r"(r[2]), "=r"(r[3]) : "r"(addr));
}

__device__ __forceinline__ void mma16816(float* c, const uint32_t* a, const uint32_t* b) {
    asm volatile(
        "mma.sync.aligned.m16n8k16.row.col.f32.bf16.bf16.f32 "
        "{%0,%1,%2,%3}, {%4,%5,%6,%7}, {%8,%9}, {%0,%1,%2,%3};"
        : "+f"(c[0]), "+f"(c[1]), "+f"(c[2]), "+f"(c[3])
        : "r"(a[0]), "r"(a[1]), "r"(a[2]), "r"(a[3]), "r"(b[0]), "r"(b[1]));
}

__device__ __forceinline__ void mma_i8(int* c, const uint32_t* a, const uint32_t* b) {
    asm volatile(
        "mma.sync.aligned.m16n8k32.row.col.s32.u8.s8.s32 "
        "{%0,%1,%2,%3}, {%4,%5,%6,%7}, {%8,%9}, {%0,%1,%2,%3};"
        : "+r"(c[0]), "+r"(c[1]), "+r"(c[2]), "+r"(c[3])
        : "r"(a[0]), "r"(a[1]), "r"(a[2]), "r"(a[3]), "r"(b[0]), "r"(b[1]));
}

// ================= INT8 GEMM (layer 1): g_H[M,256] = X[M,K] @ Wq[256,K]^T =====
// CTA 128(M) x 128(N), grid (157, 2). K-chunk 64 (two k32 mma steps).
// x = (a0*256+a1)/65535, w = (b0*128 + b1p/2) * maxw/16256.
// acc0 = sum a0*b0 ; acc12 = sum (a0*b1p + a1*b0).
// out = acc0*32768*C + acc12*128*C, C = maxw/(65535*16256).
#define ISM_A0 0
#define ISM_A1 10240
#define ISM_B0 20480
#define ISM_B1 30720
#define ISTAGE 40960
#define SMEM_I8_1 (2*ISTAGE + 128*13*4)
#define SMEM_I8_2 (2*ISTAGE + 128*149*4)

__device__ __forceinline__ void loadB_i8(uint32_t sb, int c,
                                         const char* Wq0, const char* Wq1,
                                         int Kpad, int n0, int tid) {
#pragma unroll
    for (int q = 0; q < 4; q++) {
        int idx = tid + q * 256;           // 0..1023
        int plane = idx >> 9;
        int rem = idx & 511;
        int row = rem >> 2, cc = rem & 3;
        const char* src = (plane ? Wq1 : Wq0) +
                          (size_t)(n0 + row) * Kpad + c * 64 + cc * 16;
        uint32_t dst = sb + (plane ? ISM_B1 : ISM_B0) +
                       (uint32_t)(row * 80 + cc * 16);
        cp16(dst, src, 16);
    }
}

template<int MODE>   // 1 = bond (K=480), 2 = angle (K=2880)
__device__ __forceinline__ void fillA_i8(char* st, int c, const float* raw,
                                         int K, int tid) {
    int row = tid >> 1;
    int half = tid & 1;
    int kbase = c * 64 + half * 32;
    uint32_t p0[8], p1[8];
#pragma unroll
    for (int g = 0; g < 8; g++) {
        uint32_t u0 = 0, u1 = 0;
#pragma unroll
        for (int q = 0; q < 4; q++) {
            int k = kbase + g * 4 + q;
            int x16 = 0;
            if (MODE == 2 || k < K) {
                float x;
                if (MODE == 1) {
                    int j = k / 40, s = k - j * 40;
                    float d = raw[row * 13 + j];
                    float t = d - (float)s * (8.0f / 39.0f);
                    x = __expf(-t * t * 25.0f);
                } else {
                    int j = k / 20, s = k - j * 20;
                    float d = raw[row * 149 + j];
                    float t = d - (-1.0f + (float)s * (2.0f / 19.0f));
                    x = __expf(-t * t * 100.0f);
                }
                x16 = (int)(x * 65535.0f + 0.5f);
            }
            u0 |= (uint32_t)(x16 >> 8) << (8 * q);
            u1 |= (uint32_t)(x16 & 255) << (8 * q);
        }
        p0[g] = u0; p1[g] = u1;
    }
    uint32_t doff = (uint32_t)(row * 80 + half * 32);
    *(uint4*)(st + ISM_A0 + doff)      = make_uint4(p0[0], p0[1], p0[2], p0[3]);
    *(uint4*)(st + ISM_A0 + doff + 16) = make_uint4(p0[4], p0[5], p0[6], p0[7]);
    *(uint4*)(st + ISM_A1 + doff)      = make_uint4(p1[0], p1[1], p1[2], p1[3]);
    *(uint4*)(st + ISM_A1 + doff + 16) = make_uint4(p1[4], p1[5], p1[6], p1[7]);
}

template<int MODE>
__global__ __launch_bounds__(256, 1)
void gemm_i8(const float* __restrict__ srcRaw,
             const char* __restrict__ Wq0,
             const char* __restrict__ Wq1,
             int K, int Kpad, int slot) {
    extern __shared__ char smem[];
    uint32_t sbase = smem_u32(smem);
    int tid = threadIdx.x;
    int w = tid >> 5, l = tid & 31;
    int m0 = blockIdx.x * 128;
    int n0 = blockIdx.y * 128;
    int warp_m = (w >> 1) * 32;
    int warp_n = (w & 1) * 64;
    int nchunks = (K + 63) >> 6;

    // preload raw input rows into smem (read once, reused every chunk)
    float* raw = (float*)(smem + 2 * ISTAGE);
    if (MODE == 1) {
        for (int idx = tid; idx < 128 * 12; idx += 256) {
            int r = idx / 12, cc = idx - r * 12;
            raw[r * 13 + cc] = (m0 + r < NN) ? srcRaw[(size_t)(m0 + r) * 12 + cc] : 0.f;
        }
    } else {
        for (int idx = tid; idx < 128 * 144; idx += 256) {
            int r = idx / 144, cc = idx - r * 144;
            raw[r * 149 + cc] = (m0 + r < NN) ? srcRaw[(size_t)(m0 + r) * 144 + cc] : 0.f;
        }
    }
    __syncthreads();

    int acc0[2][8][4], acc12[2][8][4];
#pragma unroll
    for (int i = 0; i < 2; i++)
#pragma unroll
        for (int j = 0; j < 8; j++)
#pragma unroll
            for (int q = 0; q < 4; q++) { acc0[i][j][q] = 0; acc12[i][j][q] = 0; }

    uint32_t a_off[2];
#pragma unroll
    for (int mt = 0; mt < 2; mt++)
        a_off[mt] = (uint32_t)((warp_m + mt * 16 + (l & 15)) * 80 + ((l >> 4) * 16));
    uint32_t b_base = (uint32_t)((warp_n + (l & 15)) * 80 + ((l >> 4) * 16));

    // prologue
    loadB_i8(sbase, 0, Wq0, Wq1, Kpad, n0, tid);
    asm volatile("cp.async.commit_group;" ::: "memory");
    fillA_i8<MODE>(smem, 0, raw, K, tid);

    for (int c = 0; c < nchunks; c++) {
        if (c + 1 < nchunks) {
            int st = (c + 1) & 1;
            loadB_i8(sbase + st * ISTAGE, c + 1, Wq0, Wq1, Kpad, n0, tid);
            asm volatile("cp.async.commit_group;" ::: "memory");
            fillA_i8<MODE>(smem + st * ISTAGE, c + 1, raw, K, tid);
            asm volatile("cp.async.wait_group 1;" ::: "memory");
        } else {
            asm volatile("cp.async.wait_group 0;" ::: "memory");
        }
        __syncthreads();

        uint32_t sb = sbase + (uint32_t)((c & 1) * ISTAGE);
#pragma unroll
        for (int s = 0; s < 2; s++) {
            uint32_t af[2][2][4];
#pragma unroll
            for (int mt = 0; mt < 2; mt++) {
                ldmx4(af[mt][0], sb + ISM_A0 + a_off[mt] + s * 32);
                ldmx4(af[mt][1], sb + ISM_A1 + a_off[mt] + s * 32);
            }
#pragma unroll
            for (int p = 0; p < 4; p++) {
                uint32_t r0[4], r1[4];
                ldmx4(r0, sb + ISM_B0 + b_base + (uint32_t)(p * 1280) + s * 32);
                ldmx4(r1, sb + ISM_B1 + b_base + (uint32_t)(p * 1280) + s * 32);
#pragma unroll
                for (int ntl = 0; ntl < 2; ntl++) {
                    uint32_t bb0[2] = { r0[ntl], r0[ntl + 2] };
                    uint32_t bb1[2] = { r1[ntl], r1[ntl + 2] };
                    int nt = p * 2 + ntl;
#pragma unroll
                    for (int mt = 0; mt < 2; mt++) {
                        mma_i8(acc0[mt][nt],  af[mt][0], bb0);
                        mma_i8(acc12[mt][nt], af[mt][0], bb1);
                        mma_i8(acc12[mt][nt], af[mt][1], bb0);
                    }
                }
            }
        }
        __syncthreads();
    }

    float maxw = g_wmax[slot];
    float C  = maxw * (1.0f / (65535.0f * 16256.0f));
    float s0 = 32768.0f * C;
    float s12 = 128.0f * C;
#pragma unroll
    for (int mt = 0; mt < 2; mt++) {
        int m1 = m0 + warp_m + mt * 16 + (l >> 2);
        int m2 = m1 + 8;
#pragma unroll
        for (int nt = 0; nt < 8; nt++) {
            int nc = n0 + warp_n + nt * 8 + 2 * (l & 3);
            float v0 = (float)acc0[mt][nt][0] * s0 + (float)acc12[mt][nt][0] * s12;
            float v1 = (float)acc0[mt][nt][1] * s0 + (float)acc12[mt][nt][1] * s12;
            float v2 = (float)acc0[mt][nt][2] * s0 + (float)acc12[mt][nt][2] * s12;
            float v3 = (float)acc0[mt][nt][3] * s0 + (float)acc12[mt][nt][3] * s12;
            if (m1 < NN)
                *(float2*)(g_H + (size_t)m1 * 256 + nc) = make_float2(v0, v1);
            if (m2 < NN)
                *(float2*)(g_H + (size_t)m2 * 256 + nc) = make_float2(v2, v3);
        }
    }
}

// ================= bf16x3 GEMM (layer 2, K=64) =================================
#define SM_AH 0
#define SM_AL 10240
#define SM_BH 20480
#define SM_BL 40960
#define STAGE 61440
#define SMEM_BF16 (2 * STAGE)

__device__ __forceinline__ void loadB_bf(uint32_t sb, int c,
                                         const __nv_bfloat16* Bh,
                                         const __nv_bfloat16* Bl,
                                         int K, int tid) {
#pragma unroll
    for (int q = 0; q < 4; q++) {
        int j = tid + q * 256;
        int row = j >> 2, cc = j & 3;
        uint32_t doff = (uint32_t)(row * 80 + cc * 16);
        size_t boff = (size_t)row * K + c * 32 + cc * 8;
        cp16(sb + SM_BH + doff, Bh + boff, 16);
        cp16(sb + SM_BL + doff, Bl + boff, 16);
    }
}

__device__ __forceinline__ void loadA_bf(uint32_t sb, int c,
                                         const __nv_bfloat16* Ah,
                                         const __nv_bfloat16* Al,
                                         int K, int m0, int tid) {
#pragma unroll
    for (int q = 0; q < 2; q++) {
        int j = tid + q * 256;
        int row = j >> 2, cc = j & 3;
        uint32_t doff = (uint32_t)(row * 80 + cc * 16);
        int gm = m0 + row;
        int gmc = gm < NN ? gm : 0;
        int sz = gm < NN ? 16 : 0;
        size_t aoff = (size_t)gmc * K + c * 32 + cc * 8;
        cp16(sb + SM_AH + doff, Ah + aoff, sz);
        cp16(sb + SM_AL + doff, Al + aoff, sz);
    }
}

__global__ __launch_bounds__(256, 1)
void gemm_bf16(const __nv_bfloat16* __restrict__ Ah,
               const __nv_bfloat16* __restrict__ Al,
               const __nv_bfloat16* __restrict__ Bh,
               const __nv_bfloat16* __restrict__ Bl,
               int K) {
    extern __shared__ char smem[];
    uint32_t sbase = smem_u32(smem);
    int tid = threadIdx.x;
    int w = tid >> 5, l = tid & 31;
    int m0 = blockIdx.x * 128;
    int warp_m = (w >> 1) * 32;
    int warp_n = (w & 1) * 128;
    int nchunks = K >> 5;

    float acc[2][16][4];
#pragma unroll
    for (int i = 0; i < 2; i++)
#pragma unroll
        for (int j = 0; j < 16; j++)
#pragma unroll
            for (int q = 0; q < 4; q++) acc[i][j][q] = 0.f;

    uint32_t a_off[2];
#pragma unroll
    for (int mt = 0; mt < 2; mt++)
        a_off[mt] = (uint32_t)((warp_m + mt * 16 + (l & 15)) * 80 + ((l >> 4) * 16));
    uint32_t b_base = (uint32_t)((warp_n + (l & 7) + ((l >> 4) << 3)) * 80 +
                                 (((l >> 3) & 1) * 16));

    loadB_bf(sbase, 0, Bh, Bl, K, tid);
    loadA_bf(sbase, 0, Ah, Al, K, m0, tid);
    asm volatile("cp.async.commit_group;" ::: "memory");

    for (int c = 0; c < nchunks; c++) {
        if (c + 1 < nchunks) {
            int st = (c + 1) & 1;
            uint32_t sb = sbase + st * STAGE;
            loadB_bf(sb, c + 1, Bh, Bl, K, tid);
            loadA_bf(sb, c + 1, Ah, Al, K, m0, tid);
            asm volatile("cp.async.commit_group;" ::: "memory");
            asm volatile("cp.async.wait_group 1;" ::: "memory");
        } else {
            asm volatile("cp.async.wait_group 0;" ::: "memory");
        }
        __syncthreads();

        uint32_t sb = sbase + (uint32_t)((c & 1) * STAGE);
#pragma unroll
        for (int s = 0; s < 2; s++) {
            uint32_t af[2][2][4];
#pragma unroll
            for (int mt = 0; mt < 2; mt++) {
                ldmx4(af[mt][0], sb + SM_AH + a_off[mt] + s * 32);
                ldmx4(af[mt][1], sb + SM_AL + a_off[mt] + s * 32);
            }
#pragma unroll
            for (int p = 0; p < 8; p++) {
                uint32_t rh[4], rl[4];
                ldmx4(rh, sb + SM_BH + b_base + (uint32_t)(p * 16 * 80) + s * 32);
                ldmx4(rl, sb + SM_BL + b_base + (uint32_t)(p * 16 * 80) + s * 32);
#pragma unroll
                for (int mt = 0; mt < 2; mt++) {
                    mma16816(acc[mt][2 * p],     af[mt][0], rh);
                    mma16816(acc[mt][2 * p],     af[mt][0], rl);
                    mma16816(acc[mt][2 * p],     af[mt][1], rh);
                    mma16816(acc[mt][2 * p + 1], af[mt][0], rh + 2);
                    mma16816(acc[mt][2 * p + 1], af[mt][0], rl + 2);
                    mma16816(acc[mt][2 * p + 1], af[mt][1], rh + 2);
                }
            }
        }
        __syncthreads();
    }

#pragma unroll
    for (int mt = 0; mt < 2; mt++) {
        int m1 = m0 + warp_m + mt * 16 + (l >> 2);
        int m2 = m1 + 8;
#pragma unroll
        for (int nt = 0; nt < 16; nt++) {
            int nc = warp_n + nt * 8 + 2 * (l & 3);
            if (m1 < NN)
                *(float2*)(g_H + (size_t)m1 * 256 + nc) =
                    make_float2(acc[mt][nt][0], acc[mt][nt][1]);
            if (m2 < NN)
                *(float2*)(g_H + (size_t)m2 * 256 + nc) =
                    make_float2(acc[mt][nt][2], acc[mt][nt][3]);
        }
    }
}

// ---------------- weight prep ----------------------------------------------------
__global__ void wmax_kernel(const float* __restrict__ Wroot,
                            const float* __restrict__ Wrel, int K, int slot) {
    int n = K * 64;
    float m = 0.f;
    for (int i = blockIdx.x * blockDim.x + threadIdx.x; i < 4 * n;
         i += gridDim.x * blockDim.x) {
        float w = (i < n) ? Wroot[i] : Wrel[i - n];
        m = fmaxf(m, fabsf(w));
    }
#pragma unroll
    for (int o = 16; o; o >>= 1)
        m = fmaxf(m, __shfl_xor_sync(0xFFFFFFFFu, m, o));
    if ((threadIdx.x & 31) == 0)
        atomicMax((int*)&g_wmax[slot], __float_as_int(m));
}

__global__ void quant_w(const float* __restrict__ Wroot,
                        const float* __restrict__ Wrel, int K, int Kpad, int slot) {
    __shared__ float sm[32][65];
    int tid = threadIdx.x;
    int k0 = blockIdx.x * 32;
    int cb = blockIdx.y;
    float scale = 16256.0f / g_wmax[slot];
#pragma unroll
    for (int i = 0; i < 8; i++) {
        int e = tid + i * 256;
        int k = e >> 6, h = e & 63;
        float wv = 0.f;
        if (k0 + k < K)
            wv = (cb == 0) ? Wroot[(size_t)(k0 + k) * 64 + h]
                           : Wrel[(size_t)(cb - 1) * K * 64 + (size_t)(k0 + k) * 64 + h];
        sm[k][h] = wv;
    }
    __syncthreads();
#pragma unroll
    for (int i = 0; i < 8; i++) {
        int e = tid + i * 256;
        int h = e >> 5, kk = e & 31;
        int w15 = (int)rintf(sm[kk][h] * scale);
        int b0 = (w15 + 64) >> 7;
        int b1 = w15 - (b0 << 7);
        size_t o = (size_t)(cb * 64 + h) * Kpad + k0 + kk;
        g_Wq0[o] = (char)b0;
        g_Wq1[o] = (char)(b1 * 2);
    }
}

__global__ void prep_wT(const float* __restrict__ Wroot,
                        const float* __restrict__ Wrel, int K) {
    __shared__ float sm[32][65];
    int tid = threadIdx.x;
    int k0 = blockIdx.x * 32;
    int cb = blockIdx.y;
#pragma unroll
    for (int i = 0; i < 8; i++) {
        int e = tid + i * 256;
        int k = e >> 6, h = e & 63;
        float wv = (cb == 0) ? Wroot[(size_t)(k0 + k) * 64 + h]
                             : Wrel[(size_t)(cb - 1) * K * 64 + (size_t)(k0 + k) * 64 + h];
        sm[k][h] = wv;
    }
    __syncthreads();
#pragma unroll
    for (int i = 0; i < 8; i++) {
        int e = tid + i * 256;
        int h = e >> 5, kk = e & 31;
        float wv = sm[kk][h];
        __nv_bfloat16 hi = __float2bfloat16(wv);
        float lo = wv - __bfloat162float(hi);
        size_t o = (size_t)(cb * 64 + h) * K + k0 + kk;
        g_Wth[o] = hi;
        g_Wtl[o] = __float2bfloat16(lo);
    }
}

// ---------------- graph preprocessing ------------------------------------------
__global__ void zero_kernel() {
    int i = blockIdx.x * blockDim.x + threadIdx.x;
    if (i < NN * 3) g_cnt[i] = 0;
    if (i < NN) g_deg[i] = 0;
    if (i < NCRYS * 128) g_pool[i] = 0.f;
    if (i < 2) g_wmax[i] = 0.f;
}

__global__ void count_kernel(const int* __restrict__ nbr,
                             const int* __restrict__ species) {
    int e = blockIdx.x * blockDim.x + threadIdx.x;
    if (e >= EE) return;
    int src = e / NEIGH;
    int dst = nbr[e];
    int et = species[src] + species[dst];
    atomicAdd(&g_cnt[dst * 3 + et], 1);
    atomicAdd(&g_deg[dst], 1);
}

__global__ void scan_kernel() {
    __shared__ int ps[1024];
    int t = threadIdx.x;
    int base = t * 20;
    int local[20];
    int s = 0;
#pragma unroll
    for (int i = 0; i < 20; i++) {
        int idx = base + i;
        int d = (idx < NN) ? g_deg[idx] : 0;
        local[i] = s;
        s += d;
    }
    ps[t] = s;
    __syncthreads();
    for (int off = 1; off < 1024; off <<= 1) {
        int v = (t >= off) ? ps[t - off] : 0;
        __syncthreads();
        ps[t] += v;
        __syncthreads();
    }
    int pre = (t > 0) ? ps[t - 1] : 0;
#pragma unroll
    for (int i = 0; i < 20; i++) {
        int idx = base + i;
        if (idx < NN) {
            g_off[idx] = pre + local[i];
            g_pos[idx] = pre + local[i];
        }
    }
    if (t == 1023) g_off[NN] = ps[1023];
}

__global__ void fill_kernel(const int* __restrict__ nbr,
                            const int* __restrict__ species) {
    int e = blockIdx.x * blockDim.x + threadIdx.x;
    if (e >= EE) return;
    int src = e / NEIGH;
    int dst = nbr[e];
    int et = species[src] + species[dst];
    int p = atomicAdd(&g_pos[dst], 1);
    g_rev[p] = (src << 2) | et;
}

// ---------------- gather aggregation --------------------------------------------
template<int OUT>
__global__ void gather_kernel(const float* __restrict__ bias,
                              __nv_bfloat16* __restrict__ oh,
                              __nv_bfloat16* __restrict__ ol,
                              float* __restrict__ of) {
    int tid = threadIdx.x;
    int dst = blockIdx.x * 4 + (tid >> 6);
    int h = tid & 63;
    if (dst >= NN) return;
    int c0 = g_cnt[dst * 3 + 0], c1 = g_cnt[dst * 3 + 1], c2 = g_cnt[dst * 3 + 2];
    float inv0 = 1.0f / (float)(c0 > 0 ? c0 : 1);
    float inv1 = 1.0f / (float)(c1 > 0 ? c1 : 1);
    float inv2 = 1.0f / (float)(c2 > 0 ? c2 : 1);
    float v = g_H[(size_t)dst * 256 + h] + bias[h];
    int b0 = g_off[dst], b1 = g_off[dst + 1];
    for (int p = b0; p < b1; p++) {
        int pk = g_rev[p];
        int src = pk >> 2, et = pk & 3;
        float ic = (et == 0) ? inv0 : ((et == 1) ? inv1 : inv2);
        v += g_H[(size_t)src * 256 + (et + 1) * 64 + h] * ic;
    }
    v = v > 0.f ? v : 0.f;
    if (OUT == 0) {
        __nv_bfloat16 hi = __float2bfloat16(v);
        oh[dst * 64 + h] = hi;
        ol[dst * 64 + h] = __float2bfloat16(v - __bfloat162float(hi));
    } else {
        of[dst * 64 + h] = v;
    }
}

// ---------------- pooling + FC ---------------------------------------------------
#define POOL_NODES 160
__global__ void pool_kernel(const int* __restrict__ crys) {
    __shared__ int starts[NCRYS];
    int t = threadIdx.x;
    if (t < NCRYS) starts[t] = crys[t * 2];
    __syncthreads();
    int v0 = blockIdx.x * POOL_NODES;
    int v1 = v0 + POOL_NODES;
    if (v1 > NN) v1 = NN;
    const float* srcbuf = (t < 64) ? g_bf : g_af;
    int h = t & 63;
    float sum = 0.f;
    int cur = -2;
    for (int v = v0; v < v1; v++) {
        int c = 0;
#pragma unroll
        for (int k = 1; k < NCRYS; k++)
            if (starts[k] <= v) c = k;
        if (c != cur) {
            if (cur >= 0) atomicAdd(&g_pool[cur * 128 + t], sum);
            sum = 0.f;
            cur = c;
        }
        sum += srcbuf[v * 64 + h];
    }
    if (cur >= 0) atomicAdd(&g_pool[cur * 128 + t], sum);
}

__global__ void fc_kernel(const int* __restrict__ crys,
                          const float* __restrict__ W,
                          const float* __restrict__ b,
                          float* __restrict__ out) {
    int t = threadIdx.x;
    if (t >= NCRYS * 2) return;
    int c = t >> 1, o = t & 1;
    float cnt = (float)(crys[c * 2 + 1] - crys[c * 2]);
    float inv = 1.0f / cnt;
    float s = 0.f;
    for (int h = 0; h < 128; h++)
        s += g_pool[c * 128 + h] * inv * W[h * 2 + o];
    out[t] = s + b[o];
}

// ---------------- launch ----------------------------------------------------------
extern "C" void kernel_launch(void* const* d_in, const int* in_sizes, int n_in,
                              void* d_out, int out_size) {
    const float* bond     = (const float*)d_in[0];
    const float* angle    = (const float*)d_in[1];
    const int*   species  = (const int*)d_in[2];
    const int*   nbr      = (const int*)d_in[3];
    const int*   crys     = (const int*)d_in[4];
    const float* W1b_rel  = (const float*)d_in[5];
    const float* W1b_root = (const float*)d_in[6];
    const float* b1b      = (const float*)d_in[7];
    const float* W1a_rel  = (const float*)d_in[8];
    const float* W1a_root = (const float*)d_in[9];
    const float* b1a      = (const float*)d_in[10];
    const float* W2b_rel  = (const float*)d_in[11];
    const float* W2b_root = (const float*)d_in[12];
    const float* b2b      = (const float*)d_in[13];
    const float* W2a_rel  = (const float*)d_in[14];
    const float* W2a_root = (const float*)d_in[15];
    const float* b2a      = (const float*)d_in[16];
    const float* fcW      = (const float*)d_in[17];
    const float* fcb      = (const float*)d_in[18];
    float* out = (float*)d_out;

    cudaFuncSetAttribute(gemm_i8<1>, cudaFuncAttributeMaxDynamicSharedMemorySize, SMEM_I8_1);
    cudaFuncSetAttribute(gemm_i8<2>, cudaFuncAttributeMaxDynamicSharedMemorySize, SMEM_I8_2);
    cudaFuncSetAttribute(gemm_bf16,  cudaFuncAttributeMaxDynamicSharedMemorySize, SMEM_BF16);

    char *Wq0, *Wq1;
    __nv_bfloat16 *Wth, *Wtl, *bfh, *bfl, *afh, *afl;
    float *bfp, *afp;
    cudaGetSymbolAddress((void**)&Wq0, g_Wq0);
    cudaGetSymbolAddress((void**)&Wq1, g_Wq1);
    cudaGetSymbolAddress((void**)&Wth, g_Wth);
    cudaGetSymbolAddress((void**)&Wtl, g_Wtl);
    cudaGetSymbolAddress((void**)&bfh, g_bfh);
    cudaGetSymbolAddress((void**)&bfl, g_bfl);
    cudaGetSymbolAddress((void**)&afh, g_afh);
    cudaGetSymbolAddress((void**)&afl, g_afl);
    cudaGetSymbolAddress((void**)&bfp, g_bf);
    cudaGetSymbolAddress((void**)&afp, g_af);

    const int T = 256;
    dim3 igrid((NN + 127) / 128, 2);     // (157, 2)
    const int GBLK = (NN + 127) / 128;   // 157
    const int GGRID = (NN + 3) / 4;

    // graph preprocessing
    zero_kernel<<<(NN * 3 + T - 1) / T, T>>>();
    count_kernel<<<(EE + T - 1) / T, T>>>(nbr, species);
    scan_kernel<<<1, 1024>>>();
    fill_kernel<<<(EE + T - 1) / T, T>>>(nbr, species);

    // --- bond, layer 1 (int8, fused expansion, Kpad=512)
    wmax_kernel<<<120, 256>>>(W1b_root, W1b_rel, INB, 0);
    quant_w<<<dim3(512 / 32, 4), 256>>>(W1b_root, W1b_rel, INB, 512, 0);
    gemm_i8<1><<<igrid, 256, SMEM_I8_1>>>(bond, Wq0, Wq1, INB, 512, 0);
    gather_kernel<0><<<GGRID, 256>>>(b1b, bfh, bfl, nullptr);

    // --- angle, layer 1 (int8, fused expansion)
    wmax_kernel<<<240, 256>>>(W1a_root, W1a_rel, INA, 1);
    quant_w<<<dim3(INA / 32, 4), 256>>>(W1a_root, W1a_rel, INA, INA, 1);
    gemm_i8<2><<<igrid, 256, SMEM_I8_2>>>(angle, Wq0, Wq1, INA, INA, 1);
    gather_kernel<0><<<GGRID, 256>>>(b1a, afh, afl, nullptr);

    // --- bond, layer 2 (bf16x3)
    prep_wT<<<dim3(HD / 32, 4), 256>>>(W2b_root, W2b_rel, HD);
    gemm_bf16<<<GBLK, 256, SMEM_BF16>>>(bfh, bfl, Wth, Wtl, HD);
    gather_kernel<1><<<GGRID, 256>>>(b2b, nullptr, nullptr, bfp);

    // --- angle, layer 2 (bf16x3)
    prep_wT<<<dim3(HD / 32, 4), 256>>>(W2a_root, W2a_rel, HD);
    gemm_bf16<<<GBLK, 256, SMEM_BF16>>>(afh, afl, Wth, Wtl, HD);
    gather_kernel<1><<<GGRID, 256>>>(b2a, nullptr, nullptr, afp);

    // --- pooling + FC
    pool_kernel<<<(NN + POOL_NODES - 1) / POOL_NODES, 128>>>(crys);
    fc_kernel<<<1, 64>>>(crys, fcW, fcb, out);
}

// round 8
// speedup vs baseline: 1.6664x; 1.6664x over previous
#include <cuda_runtime.h>
#include <cuda_bf16.h>
#include <cstdint>

#define NN     20000
#define NEIGH  12
#define EE     (NN*NEIGH)
#define HD     64
#define INB    480
#define INA    2880
#define NCRYS  20

// ---------------- scratch ----------------------------------------------------
__device__ __align__(256) __nv_bfloat16 g_Wth[256 * INA];
__device__ __align__(256) __nv_bfloat16 g_Wtl[256 * INA];
__device__ float g_H[(size_t)NN * 256];
__device__ float g_bf[NN * HD];
__device__ float g_af[NN * HD];
__device__ __align__(256) __nv_bfloat16 g_bfh[NN * HD], g_bfl[NN * HD];
__device__ __align__(256) __nv_bfloat16 g_afh[NN * HD], g_afl[NN * HD];
__device__ int   g_cnt[NN * 3];
__device__ int   g_deg[NN];
__device__ int   g_off[NN + 1];
__device__ int   g_pos[NN];
__device__ int   g_rev[EE];
__device__ float g_pool[NCRYS * 128];

// ---------------- helpers ------------------------------------------------------
__device__ __forceinline__ uint32_t smem_u32(const void* p) {
    uint32_t a;
    asm("{ .reg .u64 t; cvta.to.shared.u64 t, %1; cvt.u32.u64 %0, t; }"
        : "=r"(a) : "l"(p));
    return a;
}

__device__ __forceinline__ void cp16(uint32_t dst, const void* src, int sz) {
    asm volatile("cp.async.cg.shared.global [%0], [%1], 16, %2;"
                 :: "r"(dst), "l"(src), "r"(sz));
}

__device__ __forceinline__ void ldmx4(uint32_t* r, uint32_t addr) {
    asm volatile("ldmatrix.sync.aligned.m8n8.x4.shared.b16 {%0,%1,%2,%3}, [%4];"
                 : "=r"(r[0]), "=r"(r[1]), "=r"(r[2]), "=r"(r[3]) : "r"(addr));
}

__device__ __forceinline__ void mma16816(float* c, const uint32_t* a, const uint32_t* b) {
    asm volatile(
        "mma.sync.aligned.m16n8k16.row.col.f32.bf16.bf16.f32 "
        "{%0,%1,%2,%3}, {%4,%5,%6,%7}, {%8,%9}, {%0,%1,%2,%3};"
        : "+f"(c[0]), "+f"(c[1]), "+f"(c[2]), "+f"(c[3])
        : "r"(a[0]), "r"(a[1]), "r"(a[2]), "r"(a[3]), "r"(b[0]), "r"(b[1]));
}

// ---------------- GEMM: g_H[M,256] = X[M,K] @ Wt[256,K]^T (bf16x3) -------------
// CTA tile 128(M) x 256(N), 512 threads (16 warps -> 4 warps/SMSP).
// Warp tile 32(M) x 64(N). K-chunk 32, 2-stage cp.async pipeline.
// MODE 0: A from bf16 hi/lo buffers. MODE 1: bond expansion fused. MODE 2: angle.
#define SM_AH 0
#define SM_AL 10240
#define SM_BH 20480
#define SM_BL 40960
#define STAGE 61440
#define SMEM_GEMM (2 * STAGE)

__device__ __forceinline__ void loadB_bf(uint32_t sb, int c,
                                         const __nv_bfloat16* Bh,
                                         const __nv_bfloat16* Bl,
                                         int K, int tid) {
#pragma unroll
    for (int q = 0; q < 4; q++) {
        int idx = tid + q * 512;            // 0..2047
        int plane = idx >> 10;
        int rem = idx & 1023;
        int row = rem >> 2, cc = rem & 3;
        const __nv_bfloat16* src = (plane ? Bl : Bh) + (size_t)row * K + c * 32 + cc * 8;
        uint32_t dst = sb + (plane ? SM_BL : SM_BH) + (uint32_t)(row * 80 + cc * 16);
        cp16(dst, src, 16);
    }
}

__device__ __forceinline__ void loadA_bf(uint32_t sb, int c,
                                         const __nv_bfloat16* Ah,
                                         const __nv_bfloat16* Al,
                                         int K, int m0, int tid) {
    int row = tid >> 2, cc = tid & 3;
    uint32_t doff = (uint32_t)(row * 80 + cc * 16);
    int gm = m0 + row;
    int gmc = gm < NN ? gm : 0;
    int sz = gm < NN ? 16 : 0;
    size_t aoff = (size_t)gmc * K + c * 32 + cc * 8;
    cp16(sb + SM_AH + doff, Ah + aoff, sz);
    cp16(sb + SM_AL + doff, Al + aoff, sz);
}

template<int MODE>
__device__ __forceinline__ void fillA_expand(char* st, int c, const float* src,
                                             int m0, int tid) {
    int row = tid >> 2;
    int q4  = tid & 3;
    int gr  = m0 + row;
    int kbase = c * 32 + q4 * 8;
    uint32_t hb[4], lb[4];
    if (gr < NN) {
#pragma unroll
        for (int i = 0; i < 4; i++) {
            float xs[2];
#pragma unroll
            for (int q = 0; q < 2; q++) {
                int k = kbase + i * 2 + q;
                float x;
                if (MODE == 1) {
                    int j = k / 40, s = k - j * 40;
                    float d = src[gr * NEIGH + j];
                    float t = d - (float)s * (8.0f / 39.0f);
                    x = __expf(-t * t * 25.0f);
                } else {
                    int j = k / 20, s = k - j * 20;
                    float d = src[gr * 144 + j];
                    float t = d - (-1.0f + (float)s * (2.0f / 19.0f));
                    x = __expf(-t * t * 100.0f);
                }
                xs[q] = x;
            }
            __nv_bfloat16 h0 = __float2bfloat16(xs[0]);
            __nv_bfloat16 h1 = __float2bfloat16(xs[1]);
            __nv_bfloat16 l0 = __float2bfloat16(xs[0] - __bfloat162float(h0));
            __nv_bfloat16 l1 = __float2bfloat16(xs[1] - __bfloat162float(h1));
            hb[i] = ((uint32_t)__bfloat16_as_ushort(h1) << 16) | __bfloat16_as_ushort(h0);
            lb[i] = ((uint32_t)__bfloat16_as_ushort(l1) << 16) | __bfloat16_as_ushort(l0);
        }
    } else {
#pragma unroll
        for (int i = 0; i < 4; i++) { hb[i] = 0u; lb[i] = 0u; }
    }
    uint32_t doff = (uint32_t)(row * 80 + q4 * 16);
    *(uint4*)(st + SM_AH + doff) = make_uint4(hb[0], hb[1], hb[2], hb[3]);
    *(uint4*)(st + SM_AL + doff) = make_uint4(lb[0], lb[1], lb[2], lb[3]);
}

template<int MODE>
__global__ __launch_bounds__(512, 1)
void gemm_mma(const void* A0v, const void* A1v,
              const __nv_bfloat16* __restrict__ Bh,
              const __nv_bfloat16* __restrict__ Bl,
              int K) {
    extern __shared__ char smem[];
    uint32_t sbase = smem_u32(smem);
    int tid = threadIdx.x;
    int w = tid >> 5, l = tid & 31;
    int m0 = blockIdx.x * 128;
    int warp_m = (w >> 2) * 32;
    int warp_n = (w & 3) * 64;
    int nchunks = K >> 5;

    float acc[2][8][4];
#pragma unroll
    for (int i = 0; i < 2; i++)
#pragma unroll
        for (int j = 0; j < 8; j++)
#pragma unroll
            for (int q = 0; q < 4; q++) acc[i][j][q] = 0.f;

    uint32_t a_off[2];
#pragma unroll
    for (int mt = 0; mt < 2; mt++)
        a_off[mt] = (uint32_t)((warp_m + mt * 16 + (l & 15)) * 80 + ((l >> 4) * 16));
    uint32_t b_base = (uint32_t)((warp_n + (l & 7) + ((l >> 4) << 3)) * 80 +
                                 (((l >> 3) & 1) * 16));

    // prologue: stage 0, chunk 0
    {
        loadB_bf(sbase, 0, Bh, Bl, K, tid);
        if (MODE == 0)
            loadA_bf(sbase, 0, (const __nv_bfloat16*)A0v,
                     (const __nv_bfloat16*)A1v, K, m0, tid);
        asm volatile("cp.async.commit_group;" ::: "memory");
        if (MODE != 0)
            fillA_expand<MODE>(smem, 0, (const float*)A0v, m0, tid);
    }

    for (int c = 0; c < nchunks; c++) {
        if (c + 1 < nchunks) {
            int st = (c + 1) & 1;
            uint32_t sb = sbase + st * STAGE;
            loadB_bf(sb, c + 1, Bh, Bl, K, tid);
            if (MODE == 0)
                loadA_bf(sb, c + 1, (const __nv_bfloat16*)A0v,
                         (const __nv_bfloat16*)A1v, K, m0, tid);
            asm volatile("cp.async.commit_group;" ::: "memory");
            if (MODE != 0)
                fillA_expand<MODE>(smem + st * STAGE, c + 1, (const float*)A0v, m0, tid);
            asm volatile("cp.async.wait_group 1;" ::: "memory");
        } else {
            asm volatile("cp.async.wait_group 0;" ::: "memory");
        }
        __syncthreads();

        uint32_t sb = sbase + (uint32_t)((c & 1) * STAGE);
#pragma unroll
        for (int s = 0; s < 2; s++) {
            uint32_t af[2][2][4];
#pragma unroll
            for (int mt = 0; mt < 2; mt++) {
                ldmx4(af[mt][0], sb + SM_AH + a_off[mt] + s * 32);
                ldmx4(af[mt][1], sb + SM_AL + a_off[mt] + s * 32);
            }
#pragma unroll
            for (int p = 0; p < 4; p++) {
                uint32_t rh[4], rl[4];
                ldmx4(rh, sb + SM_BH + b_base + (uint32_t)(p * 16 * 80) + s * 32);
                ldmx4(rl, sb + SM_BL + b_base + (uint32_t)(p * 16 * 80) + s * 32);
#pragma unroll
                for (int mt = 0; mt < 2; mt++) {
                    mma16816(acc[mt][2 * p],     af[mt][0], rh);
                    mma16816(acc[mt][2 * p],     af[mt][0], rl);
                    mma16816(acc[mt][2 * p],     af[mt][1], rh);
                    mma16816(acc[mt][2 * p + 1], af[mt][0], rh + 2);
                    mma16816(acc[mt][2 * p + 1], af[mt][0], rl + 2);
                    mma16816(acc[mt][2 * p + 1], af[mt][1], rh + 2);
                }
            }
        }
        __syncthreads();
    }

#pragma unroll
    for (int mt = 0; mt < 2; mt++) {
        int m1 = m0 + warp_m + mt * 16 + (l >> 2);
        int m2 = m1 + 8;
#pragma unroll
        for (int nt = 0; nt < 8; nt++) {
            int nc = warp_n + nt * 8 + 2 * (l & 3);
            if (m1 < NN)
                *(float2*)(g_H + (size_t)m1 * 256 + nc) =
                    make_float2(acc[mt][nt][0], acc[mt][nt][1]);
            if (m2 < NN)
                *(float2*)(g_H + (size_t)m2 * 256 + nc) =
                    make_float2(acc[mt][nt][2], acc[mt][nt][3]);
        }
    }
}

// ---------------- weight transpose + bf16 split --------------------------------
__global__ void prep_wT(const float* __restrict__ Wroot,
                        const float* __restrict__ Wrel, int K) {
    __shared__ float sm[32][65];
    int tid = threadIdx.x;
    int k0 = blockIdx.x * 32;
    int cb = blockIdx.y;
#pragma unroll
    for (int i = 0; i < 8; i++) {
        int e = tid + i * 256;
        int k = e >> 6, h = e & 63;
        float wv = (cb == 0) ? Wroot[(size_t)(k0 + k) * 64 + h]
                             : Wrel[(size_t)(cb - 1) * K * 64 + (size_t)(k0 + k) * 64 + h];
        sm[k][h] = wv;
    }
    __syncthreads();
#pragma unroll
    for (int i = 0; i < 8; i++) {
        int e = tid + i * 256;
        int h = e >> 5, kk = e & 31;
        float wv = sm[kk][h];
        __nv_bfloat16 hi = __float2bfloat16(wv);
        float lo = wv - __bfloat162float(hi);
        size_t o = (size_t)(cb * 64 + h) * K + k0 + kk;
        g_Wth[o] = hi;
        g_Wtl[o] = __float2bfloat16(lo);
    }
}

// ---------------- graph preprocessing ------------------------------------------
__global__ void zero_kernel() {
    int i = blockIdx.x * blockDim.x + threadIdx.x;
    if (i < NN * 3) g_cnt[i] = 0;
    if (i < NN) g_deg[i] = 0;
    if (i < NCRYS * 128) g_pool[i] = 0.f;
}

__global__ void count_kernel(const int* __restrict__ nbr,
                             const int* __restrict__ species) {
    int e = blockIdx.x * blockDim.x + threadIdx.x;
    if (e >= EE) return;
    int src = e / NEIGH;
    int dst = nbr[e];
    int et = species[src] + species[dst];
    atomicAdd(&g_cnt[dst * 3 + et], 1);
    atomicAdd(&g_deg[dst], 1);
}

__global__ void scan_kernel() {
    __shared__ int ps[1024];
    int t = threadIdx.x;
    int base = t * 20;
    int local[20];
    int s = 0;
#pragma unroll
    for (int i = 0; i < 20; i++) {
        int idx = base + i;
        int d = (idx < NN) ? g_deg[idx] : 0;
        local[i] = s;
        s += d;
    }
    ps[t] = s;
    __syncthreads();
    for (int off = 1; off < 1024; off <<= 1) {
        int v = (t >= off) ? ps[t - off] : 0;
        __syncthreads();
        ps[t] += v;
        __syncthreads();
    }
    int pre = (t > 0) ? ps[t - 1] : 0;
#pragma unroll
    for (int i = 0; i < 20; i++) {
        int idx = base + i;
        if (idx < NN) {
            g_off[idx] = pre + local[i];
            g_pos[idx] = pre + local[i];
        }
    }
    if (t == 1023) g_off[NN] = ps[1023];
}

__global__ void fill_kernel(const int* __restrict__ nbr,
                            const int* __restrict__ species) {
    int e = blockIdx.x * blockDim.x + threadIdx.x;
    if (e >= EE) return;
    int src = e / NEIGH;
    int dst = nbr[e];
    int et = species[src] + species[dst];
    int p = atomicAdd(&g_pos[dst], 1);
    g_rev[p] = (src << 2) | et;
}

// ---------------- gather aggregation --------------------------------------------
template<int OUT>
__global__ void gather_kernel(const float* __restrict__ bias,
                              __nv_bfloat16* __restrict__ oh,
                              __nv_bfloat16* __restrict__ ol,
                              float* __restrict__ of) {
    int tid = threadIdx.x;
    int dst = blockIdx.x * 4 + (tid >> 6);
    int h = tid & 63;
    if (dst >= NN) return;
    int c0 = g_cnt[dst * 3 + 0], c1 = g_cnt[dst * 3 + 1], c2 = g_cnt[dst * 3 + 2];
    float inv0 = 1.0f / (float)(c0 > 0 ? c0 : 1);
    float inv1 = 1.0f / (float)(c1 > 0 ? c1 : 1);
    float inv2 = 1.0f / (float)(c2 > 0 ? c2 : 1);
    float v = g_H[(size_t)dst * 256 + h] + bias[h];
    int b0 = g_off[dst], b1 = g_off[dst + 1];
    for (int p = b0; p < b1; p++) {
        int pk = g_rev[p];
        int src = pk >> 2, et = pk & 3;
        float ic = (et == 0) ? inv0 : ((et == 1) ? inv1 : inv2);
        v += g_H[(size_t)src * 256 + (et + 1) * 64 + h] * ic;
    }
    v = v > 0.f ? v : 0.f;
    if (OUT == 0) {
        __nv_bfloat16 hi = __float2bfloat16(v);
        oh[dst * 64 + h] = hi;
        ol[dst * 64 + h] = __float2bfloat16(v - __bfloat162float(hi));
    } else {
        of[dst * 64 + h] = v;
    }
}

// ---------------- pooling + FC ---------------------------------------------------
#define POOL_NODES 160
__global__ void pool_kernel(const int* __restrict__ crys) {
    __shared__ int starts[NCRYS];
    int t = threadIdx.x;
    if (t < NCRYS) starts[t] = crys[t * 2];
    __syncthreads();
    int v0 = blockIdx.x * POOL_NODES;
    int v1 = v0 + POOL_NODES;
    if (v1 > NN) v1 = NN;
    const float* srcbuf = (t < 64) ? g_bf : g_af;
    int h = t & 63;
    float sum = 0.f;
    int cur = -2;
    for (int v = v0; v < v1; v++) {
        int c = 0;
#pragma unroll
        for (int k = 1; k < NCRYS; k++)
            if (starts[k] <= v) c = k;
        if (c != cur) {
            if (cur >= 0) atomicAdd(&g_pool[cur * 128 + t], sum);
            sum = 0.f;
            cur = c;
        }
        sum += srcbuf[v * 64 + h];
    }
    if (cur >= 0) atomicAdd(&g_pool[cur * 128 + t], sum);
}

__global__ void fc_kernel(const int* __restrict__ crys,
                          const float* __restrict__ W,
                          const float* __restrict__ b,
                          float* __restrict__ out) {
    int t = threadIdx.x;
    if (t >= NCRYS * 2) return;
    int c = t >> 1, o = t & 1;
    float cnt = (float)(crys[c * 2 + 1] - crys[c * 2]);
    float inv = 1.0f / cnt;
    float s = 0.f;
    for (int h = 0; h < 128; h++)
        s += g_pool[c * 128 + h] * inv * W[h * 2 + o];
    out[t] = s + b[o];
}

// ---------------- launch ----------------------------------------------------------
extern "C" void kernel_launch(void* const* d_in, const int* in_sizes, int n_in,
                              void* d_out, int out_size) {
    const float* bond     = (const float*)d_in[0];
    const float* angle    = (const float*)d_in[1];
    const int*   species  = (const int*)d_in[2];
    const int*   nbr      = (const int*)d_in[3];
    const int*   crys     = (const int*)d_in[4];
    const float* W1b_rel  = (const float*)d_in[5];
    const float* W1b_root = (const float*)d_in[6];
    const float* b1b      = (const float*)d_in[7];
    const float* W1a_rel  = (const float*)d_in[8];
    const float* W1a_root = (const float*)d_in[9];
    const float* b1a      = (const float*)d_in[10];
    const float* W2b_rel  = (const float*)d_in[11];
    const float* W2b_root = (const float*)d_in[12];
    const float* b2b      = (const float*)d_in[13];
    const float* W2a_rel  = (const float*)d_in[14];
    const float* W2a_root = (const float*)d_in[15];
    const float* b2a      = (const float*)d_in[16];
    const float* fcW      = (const float*)d_in[17];
    const float* fcb      = (const float*)d_in[18];
    float* out = (float*)d_out;

    cudaFuncSetAttribute(gemm_mma<0>, cudaFuncAttributeMaxDynamicSharedMemorySize, SMEM_GEMM);
    cudaFuncSetAttribute(gemm_mma<1>, cudaFuncAttributeMaxDynamicSharedMemorySize, SMEM_GEMM);
    cudaFuncSetAttribute(gemm_mma<2>, cudaFuncAttributeMaxDynamicSharedMemorySize, SMEM_GEMM);

    __nv_bfloat16 *Wth, *Wtl, *bfh, *bfl, *afh, *afl;
    float *bfp, *afp;
    cudaGetSymbolAddress((void**)&Wth, g_Wth);
    cudaGetSymbolAddress((void**)&Wtl, g_Wtl);
    cudaGetSymbolAddress((void**)&bfh, g_bfh);
    cudaGetSymbolAddress((void**)&bfl, g_bfl);
    cudaGetSymbolAddress((void**)&afh, g_afh);
    cudaGetSymbolAddress((void**)&afl, g_afl);
    cudaGetSymbolAddress((void**)&bfp, g_bf);
    cudaGetSymbolAddress((void**)&afp, g_af);

    const int T = 256;
    const int GBLK = (NN + 127) / 128;   // 157
    const int GGRID = (NN + 3) / 4;

    // launch order chosen so the angle GEMM sits at the ncu-captured slot (index 3)
    zero_kernel<<<(NN * 3 + T - 1) / T, T>>>();                          // 0
    count_kernel<<<(EE + T - 1) / T, T>>>(nbr, species);                 // 1
    prep_wT<<<dim3(INA / 32, 4), 256>>>(W1a_root, W1a_rel, INA);         // 2
    gemm_mma<2><<<GBLK, 512, SMEM_GEMM>>>(angle, nullptr, Wth, Wtl, INA); // 3 <- profiled
    scan_kernel<<<1, 1024>>>();                                          // 4
    fill_kernel<<<(EE + T - 1) / T, T>>>(nbr, species);                  // 5
    gather_kernel<0><<<GGRID, 256>>>(b1a, afh, afl, nullptr);            // 6

    // --- bond, layer 1 (fused expansion)
    prep_wT<<<dim3(INB / 32, 4), 256>>>(W1b_root, W1b_rel, INB);
    gemm_mma<1><<<GBLK, 512, SMEM_GEMM>>>(bond, nullptr, Wth, Wtl, INB);
    gather_kernel<0><<<GGRID, 256>>>(b1b, bfh, bfl, nullptr);

    // --- bond, layer 2
    prep_wT<<<dim3(HD / 32, 4), 256>>>(W2b_root, W2b_rel, HD);
    gemm_mma<0><<<GBLK, 512, SMEM_GEMM>>>(bfh, bfl, Wth, Wtl, HD);
    gather_kernel<1><<<GGRID, 256>>>(b2b, nullptr, nullptr, bfp);

    // --- angle, layer 2
    prep_wT<<<dim3(HD / 32, 4), 256>>>(W2a_root, W2a_rel, HD);
    gemm_mma<0><<<GBLK, 512, SMEM_GEMM>>>(afh, afl, Wth, Wtl, HD);
    gather_kernel<1><<<GGRID, 256>>>(b2a, nullptr, nullptr, afp);

    // --- pooling + FC
    pool_kernel<<<(NN + POOL_NODES - 1) / POOL_NODES, 128>>>(crys);
    fc_kernel<<<1, 64>>>(crys, fcW, fcb, out);
}

// round 9
// speedup vs baseline: 1.7325x; 1.0396x over previous
#include <cuda_runtime.h>
#include <cuda_bf16.h>
#include <cstdint>

#define NN     20000
#define NEIGH  12
#define EE     (NN*NEIGH)
#define HD     64
#define INB    480
#define INA    2880
#define NCRYS  20

// ---------------- scratch ----------------------------------------------------
__device__ __align__(256) __nv_bfloat16 g_Wth[256 * INA];
__device__ __align__(256) __nv_bfloat16 g_Wtl[256 * INA];
__device__ float g_H[(size_t)NN * 256];
__device__ float g_bf[NN * HD];
__device__ float g_af[NN * HD];
__device__ __align__(256) __nv_bfloat16 g_bfh[NN * HD], g_bfl[NN * HD];
__device__ __align__(256) __nv_bfloat16 g_afh[NN * HD], g_afl[NN * HD];
__device__ int   g_cnt[NN * 3];
__device__ int   g_deg[NN];
__device__ int   g_off[NN + 1];
__device__ int   g_pos[NN];
__device__ int   g_rev[EE];
__device__ float g_pool[NCRYS * 128];

// ---------------- helpers ------------------------------------------------------
__device__ __forceinline__ uint32_t smem_u32(const void* p) {
    uint32_t a;
    asm("{ .reg .u64 t; cvta.to.shared.u64 t, %1; cvt.u32.u64 %0, t; }"
        : "=r"(a) : "l"(p));
    return a;
}

__device__ __forceinline__ void cp16(uint32_t dst, const void* src, int sz) {
    asm volatile("cp.async.cg.shared.global [%0], [%1], 16, %2;"
                 :: "r"(dst), "l"(src), "r"(sz));
}

__device__ __forceinline__ void ldmx4(uint32_t* r, uint32_t addr) {
    asm volatile("ldmatrix.sync.aligned.m8n8.x4.shared.b16 {%0,%1,%2,%3}, [%4];"
                 : "=r"(r[0]), "=r"(r[1]), "=r"(r[2]), "=r"(r[3]) : "r"(addr));
}

__device__ __forceinline__ void mma16816(float* c, const uint32_t* a, const uint32_t* b) {
    asm volatile(
        "mma.sync.aligned.m16n8k16.row.col.f32.bf16.bf16.f32 "
        "{%0,%1,%2,%3}, {%4,%5,%6,%7}, {%8,%9}, {%0,%1,%2,%3};"
        : "+f"(c[0]), "+f"(c[1]), "+f"(c[2]), "+f"(c[3])
        : "r"(a[0]), "r"(a[1]), "r"(a[2]), "r"(a[3]), "r"(b[0]), "r"(b[1]));
}

// ---------------- GEMM: g_H[M,256] = X[M,K] @ Wt[256,K]^T (bf16x3) -------------
// CTA tile 128(M) x 128(N), 256 threads, grid (157, 2) -> 2 CTAs per SM.
// K-chunk 32, 2-stage cp.async pipeline. smem rows padded to 80B.
// MODE 0: A from bf16 hi/lo buffers. MODE 1: bond fused. MODE 2: angle fused.
#define SM_AH 0
#define SM_AL 10240
#define SM_BH 20480
#define SM_BL 30720
#define STAGE 40960
#define SMEM_GEMM (2 * STAGE)

__device__ __forceinline__ void loadB_bf(uint32_t sb, int c,
                                         const __nv_bfloat16* Bh,
                                         const __nv_bfloat16* Bl,
                                         int K, int n0, int tid) {
#pragma unroll
    for (int q = 0; q < 4; q++) {
        int idx = tid + q * 256;            // 0..1023
        int plane = idx >> 9;
        int rem = idx & 511;
        int row = rem >> 2, cc = rem & 3;
        const __nv_bfloat16* src = (plane ? Bl : Bh) +
                                   (size_t)(n0 + row) * K + c * 32 + cc * 8;
        uint32_t dst = sb + (plane ? SM_BL : SM_BH) + (uint32_t)(row * 80 + cc * 16);
        cp16(dst, src, 16);
    }
}

__device__ __forceinline__ void loadA_bf(uint32_t sb, int c,
                                         const __nv_bfloat16* Ah,
                                         const __nv_bfloat16* Al,
                                         int K, int m0, int tid) {
#pragma unroll
    for (int q = 0; q < 2; q++) {
        int j = tid + q * 256;
        int row = j >> 2, cc = j & 3;
        uint32_t doff = (uint32_t)(row * 80 + cc * 16);
        int gm = m0 + row;
        int gmc = gm < NN ? gm : 0;
        int sz = gm < NN ? 16 : 0;
        size_t aoff = (size_t)gmc * K + c * 32 + cc * 8;
        cp16(sb + SM_AH + doff, Ah + aoff, sz);
        cp16(sb + SM_AL + doff, Al + aoff, sz);
    }
}

template<int MODE>
__device__ __forceinline__ void fillA_expand(char* st, int c, const float* src,
                                             int m0, int tid) {
    int row = tid >> 1;
    int kb  = (tid & 1) * 16;
    int gr  = m0 + row;
    uint32_t hb[8], lb[8];
    if (gr < NN) {
#pragma unroll
        for (int i = 0; i < 8; i++) {
            float xs[2];
#pragma unroll
            for (int q = 0; q < 2; q++) {
                int k = c * 32 + kb + i * 2 + q;
                float x;
                if (MODE == 1) {
                    int j = k / 40, s = k - j * 40;
                    float d = src[gr * NEIGH + j];
                    float t = d - (float)s * (8.0f / 39.0f);
                    x = __expf(-t * t * 25.0f);
                } else {
                    int j = k / 20, s = k - j * 20;
                    float d = src[gr * 144 + j];
                    float t = d - (-1.0f + (float)s * (2.0f / 19.0f));
                    x = __expf(-t * t * 100.0f);
                }
                xs[q] = x;
            }
            __nv_bfloat16 h0 = __float2bfloat16(xs[0]);
            __nv_bfloat16 h1 = __float2bfloat16(xs[1]);
            __nv_bfloat16 l0 = __float2bfloat16(xs[0] - __bfloat162float(h0));
            __nv_bfloat16 l1 = __float2bfloat16(xs[1] - __bfloat162float(h1));
            hb[i] = ((uint32_t)__bfloat16_as_ushort(h1) << 16) | __bfloat16_as_ushort(h0);
            lb[i] = ((uint32_t)__bfloat16_as_ushort(l1) << 16) | __bfloat16_as_ushort(l0);
        }
    } else {
#pragma unroll
        for (int i = 0; i < 8; i++) { hb[i] = 0u; lb[i] = 0u; }
    }
    uint32_t doff = (uint32_t)(row * 80 + kb * 2);
    *(uint4*)(st + SM_AH + doff)      = make_uint4(hb[0], hb[1], hb[2], hb[3]);
    *(uint4*)(st + SM_AH + doff + 16) = make_uint4(hb[4], hb[5], hb[6], hb[7]);
    *(uint4*)(st + SM_AL + doff)      = make_uint4(lb[0], lb[1], lb[2], lb[3]);
    *(uint4*)(st + SM_AL + doff + 16) = make_uint4(lb[4], lb[5], lb[6], lb[7]);
}

template<int MODE>
__global__ __launch_bounds__(256, 2)
void gemm_mma(const void* A0v, const void* A1v,
              const __nv_bfloat16* __restrict__ Bh,
              const __nv_bfloat16* __restrict__ Bl,
              int K) {
    extern __shared__ char smem[];
    uint32_t sbase = smem_u32(smem);
    int tid = threadIdx.x;
    int w = tid >> 5, l = tid & 31;
    int m0 = blockIdx.x * 128;
    int n0 = blockIdx.y * 128;
    int warp_m = (w >> 1) * 32;
    int warp_n = (w & 1) * 64;
    int nchunks = K >> 5;

    float acc[2][8][4];
#pragma unroll
    for (int i = 0; i < 2; i++)
#pragma unroll
        for (int j = 0; j < 8; j++)
#pragma unroll
            for (int q = 0; q < 4; q++) acc[i][j][q] = 0.f;

    uint32_t a_off[2];
#pragma unroll
    for (int mt = 0; mt < 2; mt++)
        a_off[mt] = (uint32_t)((warp_m + mt * 16 + (l & 15)) * 80 + ((l >> 4) * 16));
    uint32_t b_base = (uint32_t)((warp_n + (l & 7) + ((l >> 4) << 3)) * 80 +
                                 (((l >> 3) & 1) * 16));

    // prologue: stage 0, chunk 0
    {
        loadB_bf(sbase, 0, Bh, Bl, K, n0, tid);
        if (MODE == 0)
            loadA_bf(sbase, 0, (const __nv_bfloat16*)A0v,
                     (const __nv_bfloat16*)A1v, K, m0, tid);
        asm volatile("cp.async.commit_group;" ::: "memory");
        if (MODE != 0)
            fillA_expand<MODE>(smem, 0, (const float*)A0v, m0, tid);
    }

    for (int c = 0; c < nchunks; c++) {
        if (c + 1 < nchunks) {
            int st = (c + 1) & 1;
            uint32_t sb = sbase + st * STAGE;
            loadB_bf(sb, c + 1, Bh, Bl, K, n0, tid);
            if (MODE == 0)
                loadA_bf(sb, c + 1, (const __nv_bfloat16*)A0v,
                         (const __nv_bfloat16*)A1v, K, m0, tid);
            asm volatile("cp.async.commit_group;" ::: "memory");
            if (MODE != 0)
                fillA_expand<MODE>(smem + st * STAGE, c + 1, (const float*)A0v, m0, tid);
            asm volatile("cp.async.wait_group 1;" ::: "memory");
        } else {
            asm volatile("cp.async.wait_group 0;" ::: "memory");
        }
        __syncthreads();

        uint32_t sb = sbase + (uint32_t)((c & 1) * STAGE);
#pragma unroll
        for (int s = 0; s < 2; s++) {
            uint32_t af[2][2][4];
#pragma unroll
            for (int mt = 0; mt < 2; mt++) {
                ldmx4(af[mt][0], sb + SM_AH + a_off[mt] + s * 32);
                ldmx4(af[mt][1], sb + SM_AL + a_off[mt] + s * 32);
            }
            // process p in pairs; pass-major issue order so same-acc MMAs
            // are >= 8 instructions apart (breaks 3-deep dependent chains)
#pragma unroll
            for (int pp = 0; pp < 2; pp++) {
                uint32_t bh[2][4], bl[2][4];
#pragma unroll
                for (int pi = 0; pi < 2; pi++) {
                    uint32_t ba = sb + b_base + (uint32_t)((2 * pp + pi) * 1280) + s * 32;
                    ldmx4(bh[pi], SM_BH + ba);
                    ldmx4(bl[pi], SM_BL + ba);
                }
#pragma unroll
                for (int pass = 0; pass < 3; pass++) {
#pragma unroll
                    for (int pi = 0; pi < 2; pi++) {
                        int p = 2 * pp + pi;
#pragma unroll
                        for (int mt = 0; mt < 2; mt++) {
                            const uint32_t* aa = (pass == 2) ? af[mt][1] : af[mt][0];
                            const uint32_t* bb = (pass == 1) ? bl[pi] : bh[pi];
                            mma16816(acc[mt][2 * p],     aa, bb);
                            mma16816(acc[mt][2 * p + 1], aa, bb + 2);
                        }
                    }
                }
            }
        }
        __syncthreads();
    }

#pragma unroll
    for (int mt = 0; mt < 2; mt++) {
        int m1 = m0 + warp_m + mt * 16 + (l >> 2);
        int m2 = m1 + 8;
#pragma unroll
        for (int nt = 0; nt < 8; nt++) {
            int nc = n0 + warp_n + nt * 8 + 2 * (l & 3);
            if (m1 < NN)
                *(float2*)(g_H + (size_t)m1 * 256 + nc) =
                    make_float2(acc[mt][nt][0], acc[mt][nt][1]);
            if (m2 < NN)
                *(float2*)(g_H + (size_t)m2 * 256 + nc) =
                    make_float2(acc[mt][nt][2], acc[mt][nt][3]);
        }
    }
}

// ---------------- weight transpose + bf16 split --------------------------------
__global__ void prep_wT(const float* __restrict__ Wroot,
                        const float* __restrict__ Wrel, int K) {
    __shared__ float sm[32][65];
    int tid = threadIdx.x;
    int k0 = blockIdx.x * 32;
    int cb = blockIdx.y;
#pragma unroll
    for (int i = 0; i < 8; i++) {
        int e = tid + i * 256;
        int k = e >> 6, h = e & 63;
        float wv = (cb == 0) ? Wroot[(size_t)(k0 + k) * 64 + h]
                             : Wrel[(size_t)(cb - 1) * K * 64 + (size_t)(k0 + k) * 64 + h];
        sm[k][h] = wv;
    }
    __syncthreads();
#pragma unroll
    for (int i = 0; i < 8; i++) {
        int e = tid + i * 256;
        int h = e >> 5, kk = e & 31;
        float wv = sm[kk][h];
        __nv_bfloat16 hi = __float2bfloat16(wv);
        float lo = wv - __bfloat162float(hi);
        size_t o = (size_t)(cb * 64 + h) * K + k0 + kk;
        g_Wth[o] = hi;
        g_Wtl[o] = __float2bfloat16(lo);
    }
}

// ---------------- graph preprocessing ------------------------------------------
__global__ void zero_kernel() {
    int i = blockIdx.x * blockDim.x + threadIdx.x;
    if (i < NN * 3) g_cnt[i] = 0;
    if (i < NN) g_deg[i] = 0;
    if (i < NCRYS * 128) g_pool[i] = 0.f;
}

__global__ void count_kernel(const int* __restrict__ nbr,
                             const int* __restrict__ species) {
    int e = blockIdx.x * blockDim.x + threadIdx.x;
    if (e >= EE) return;
    int src = e / NEIGH;
    int dst = nbr[e];
    int et = species[src] + species[dst];
    atomicAdd(&g_cnt[dst * 3 + et], 1);
    atomicAdd(&g_deg[dst], 1);
}

__global__ void scan_kernel() {
    __shared__ int ps[1024];
    int t = threadIdx.x;
    int base = t * 20;
    int local[20];
    int s = 0;
#pragma unroll
    for (int i = 0; i < 20; i++) {
        int idx = base + i;
        int d = (idx < NN) ? g_deg[idx] : 0;
        local[i] = s;
        s += d;
    }
    ps[t] = s;
    __syncthreads();
    for (int off = 1; off < 1024; off <<= 1) {
        int v = (t >= off) ? ps[t - off] : 0;
        __syncthreads();
        ps[t] += v;
        __syncthreads();
    }
    int pre = (t > 0) ? ps[t - 1] : 0;
#pragma unroll
    for (int i = 0; i < 20; i++) {
        int idx = base + i;
        if (idx < NN) {
            g_off[idx] = pre + local[i];
            g_pos[idx] = pre + local[i];
        }
    }
    if (t == 1023) g_off[NN] = ps[1023];
}

__global__ void fill_kernel(const int* __restrict__ nbr,
                            const int* __restrict__ species) {
    int e = blockIdx.x * blockDim.x + threadIdx.x;
    if (e >= EE) return;
    int src = e / NEIGH;
    int dst = nbr[e];
    int et = species[src] + species[dst];
    int p = atomicAdd(&g_pos[dst], 1);
    g_rev[p] = (src << 2) | et;
}

// ---------------- gather aggregation --------------------------------------------
template<int OUT>
__global__ void gather_kernel(const float* __restrict__ bias,
                              __nv_bfloat16* __restrict__ oh,
                              __nv_bfloat16* __restrict__ ol,
                              float* __restrict__ of) {
    int tid = threadIdx.x;
    int dst = blockIdx.x * 4 + (tid >> 6);
    int h = tid & 63;
    if (dst >= NN) return;
    int c0 = g_cnt[dst * 3 + 0], c1 = g_cnt[dst * 3 + 1], c2 = g_cnt[dst * 3 + 2];
    float inv0 = 1.0f / (float)(c0 > 0 ? c0 : 1);
    float inv1 = 1.0f / (float)(c1 > 0 ? c1 : 1);
    float inv2 = 1.0f / (float)(c2 > 0 ? c2 : 1);
    float v = g_H[(size_t)dst * 256 + h] + bias[h];
    int b0 = g_off[dst], b1 = g_off[dst + 1];
    for (int p = b0; p < b1; p++) {
        int pk = g_rev[p];
        int src = pk >> 2, et = pk & 3;
        float ic = (et == 0) ? inv0 : ((et == 1) ? inv1 : inv2);
        v += g_H[(size_t)src * 256 + (et + 1) * 64 + h] * ic;
    }
    v = v > 0.f ? v : 0.f;
    if (OUT == 0) {
        __nv_bfloat16 hi = __float2bfloat16(v);
        oh[dst * 64 + h] = hi;
        ol[dst * 64 + h] = __float2bfloat16(v - __bfloat162float(hi));
    } else {
        of[dst * 64 + h] = v;
    }
}

// ---------------- pooling + FC ---------------------------------------------------
#define POOL_NODES 160
__global__ void pool_kernel(const int* __restrict__ crys) {
    __shared__ int starts[NCRYS];
    int t = threadIdx.x;
    if (t < NCRYS) starts[t] = crys[t * 2];
    __syncthreads();
    int v0 = blockIdx.x * POOL_NODES;
    int v1 = v0 + POOL_NODES;
    if (v1 > NN) v1 = NN;
    const float* srcbuf = (t < 64) ? g_bf : g_af;
    int h = t & 63;
    float sum = 0.f;
    int cur = -2;
    for (int v = v0; v < v1; v++) {
        int c = 0;
#pragma unroll
        for (int k = 1; k < NCRYS; k++)
            if (starts[k] <= v) c = k;
        if (c != cur) {
            if (cur >= 0) atomicAdd(&g_pool[cur * 128 + t], sum);
            sum = 0.f;
            cur = c;
        }
        sum += srcbuf[v * 64 + h];
    }
    if (cur >= 0) atomicAdd(&g_pool[cur * 128 + t], sum);
}

__global__ void fc_kernel(const int* __restrict__ crys,
                          const float* __restrict__ W,
                          const float* __restrict__ b,
                          float* __restrict__ out) {
    int t = threadIdx.x;
    if (t >= NCRYS * 2) return;
    int c = t >> 1, o = t & 1;
    float cnt = (float)(crys[c * 2 + 1] - crys[c * 2]);
    float inv = 1.0f / cnt;
    float s = 0.f;
    for (int h = 0; h < 128; h++)
        s += g_pool[c * 128 + h] * inv * W[h * 2 + o];
    out[t] = s + b[o];
}

// ---------------- launch ----------------------------------------------------------
extern "C" void kernel_launch(void* const* d_in, const int* in_sizes, int n_in,
                              void* d_out, int out_size) {
    const float* bond     = (const float*)d_in[0];
    const float* angle    = (const float*)d_in[1];
    const int*   species  = (const int*)d_in[2];
    const int*   nbr      = (const int*)d_in[3];
    const int*   crys     = (const int*)d_in[4];
    const float* W1b_rel  = (const float*)d_in[5];
    const float* W1b_root = (const float*)d_in[6];
    const float* b1b      = (const float*)d_in[7];
    const float* W1a_rel  = (const float*)d_in[8];
    const float* W1a_root = (const float*)d_in[9];
    const float* b1a      = (const float*)d_in[10];
    const float* W2b_rel  = (const float*)d_in[11];
    const float* W2b_root = (const float*)d_in[12];
    const float* b2b      = (const float*)d_in[13];
    const float* W2a_rel  = (const float*)d_in[14];
    const float* W2a_root = (const float*)d_in[15];
    const float* b2a      = (const float*)d_in[16];
    const float* fcW      = (const float*)d_in[17];
    const float* fcb      = (const float*)d_in[18];
    float* out = (float*)d_out;

    cudaFuncSetAttribute(gemm_mma<0>, cudaFuncAttributeMaxDynamicSharedMemorySize, SMEM_GEMM);
    cudaFuncSetAttribute(gemm_mma<1>, cudaFuncAttributeMaxDynamicSharedMemorySize, SMEM_GEMM);
    cudaFuncSetAttribute(gemm_mma<2>, cudaFuncAttributeMaxDynamicSharedMemorySize, SMEM_GEMM);

    __nv_bfloat16 *Wth, *Wtl, *bfh, *bfl, *afh, *afl;
    float *bfp, *afp;
    cudaGetSymbolAddress((void**)&Wth, g_Wth);
    cudaGetSymbolAddress((void**)&Wtl, g_Wtl);
    cudaGetSymbolAddress((void**)&bfh, g_bfh);
    cudaGetSymbolAddress((void**)&bfl, g_bfl);
    cudaGetSymbolAddress((void**)&afh, g_afh);
    cudaGetSymbolAddress((void**)&afl, g_afl);
    cudaGetSymbolAddress((void**)&bfp, g_bf);
    cudaGetSymbolAddress((void**)&afp, g_af);

    const int T = 256;
    dim3 ggrid((NN + 127) / 128, 2);   // (157, 2) -> 2 CTAs/SM
    const int GGRID = (NN + 3) / 4;

    // launch order keeps the angle GEMM at ncu-captured slot (index 3)
    zero_kernel<<<(NN * 3 + T - 1) / T, T>>>();                            // 0
    count_kernel<<<(EE + T - 1) / T, T>>>(nbr, species);                   // 1
    prep_wT<<<dim3(INA / 32, 4), 256>>>(W1a_root, W1a_rel, INA);           // 2
    gemm_mma<2><<<ggrid, 256, SMEM_GEMM>>>(angle, nullptr, Wth, Wtl, INA); // 3 <- profiled
    scan_kernel<<<1, 1024>>>();                                            // 4
    fill_kernel<<<(EE + T - 1) / T, T>>>(nbr, species);                    // 5
    gather_kernel<0><<<GGRID, 256>>>(b1a, afh, afl, nullptr);              // 6

    // --- bond, layer 1 (fused expansion)
    prep_wT<<<dim3(INB / 32, 4), 256>>>(W1b_root, W1b_rel, INB);
    gemm_mma<1><<<ggrid, 256, SMEM_GEMM>>>(bond, nullptr, Wth, Wtl, INB);
    gather_kernel<0><<<GGRID, 256>>>(b1b, bfh, bfl, nullptr);

    // --- bond, layer 2
    prep_wT<<<dim3(HD / 32, 4), 256>>>(W2b_root, W2b_rel, HD);
    gemm_mma<0><<<ggrid, 256, SMEM_GEMM>>>(bfh, bfl, Wth, Wtl, HD);
    gather_kernel<1><<<GGRID, 256>>>(b2b, nullptr, nullptr, bfp);

    // --- angle, layer 2
    prep_wT<<<dim3(HD / 32, 4), 256>>>(W2a_root, W2a_rel, HD);
    gemm_mma<0><<<ggrid, 256, SMEM_GEMM>>>(afh, afl, Wth, Wtl, HD);
    gather_kernel<1><<<GGRID, 256>>>(b2a, nullptr, nullptr, afp);

    // --- pooling + FC
    pool_kernel<<<(NN + POOL_NODES - 1) / POOL_NODES, 128>>>(crys);
    fc_kernel<<<1, 64>>>(crys, fcW, fcb, out);
}

// round 10
// speedup vs baseline: 1.8737x; 1.0815x over previous
#include <cuda_runtime.h>
#include <cuda_bf16.h>
#include <cstdint>

#define NN     20000
#define NEIGH  12
#define EE     (NN*NEIGH)
#define HD     64
#define INB    480
#define INA    2880
#define NCRYS  20

// ---------------- scratch ----------------------------------------------------
__device__ __align__(256) __nv_bfloat16 g_Xh[(size_t)NN * INA];
__device__ __align__(256) __nv_bfloat16 g_Xl[(size_t)NN * INA];
__device__ __align__(256) __nv_bfloat16 g_Wth[256 * INA];
__device__ __align__(256) __nv_bfloat16 g_Wtl[256 * INA];
__device__ float g_H[(size_t)NN * 256];
__device__ float g_bf[NN * HD];
__device__ float g_af[NN * HD];
__device__ __align__(256) __nv_bfloat16 g_bfh[NN * HD], g_bfl[NN * HD];
__device__ __align__(256) __nv_bfloat16 g_afh[NN * HD], g_afl[NN * HD];
__device__ int   g_cnt[NN * 3];
__device__ int   g_deg[NN];
__device__ int   g_off[NN + 1];
__device__ int   g_pos[NN];
__device__ int   g_rev[EE];
__device__ float g_pool[NCRYS * 128];

// ---------------- helpers ------------------------------------------------------
__device__ __forceinline__ uint32_t smem_u32(const void* p) {
    uint32_t a;
    asm("{ .reg .u64 t; cvta.to.shared.u64 t, %1; cvt.u32.u64 %0, t; }"
        : "=r"(a) : "l"(p));
    return a;
}

__device__ __forceinline__ void cp16(uint32_t dst, const void* src, int sz) {
    asm volatile("cp.async.cg.shared.global [%0], [%1], 16, %2;"
                 :: "r"(dst), "l"(src), "r"(sz));
}

__device__ __forceinline__ void ldmx4(uint32_t* r, uint32_t addr) {
    asm volatile("ldmatrix.sync.aligned.m8n8.x4.shared.b16 {%0,%1,%2,%3}, [%4];"
                 : "=r"(r[0]), "=r"(r[1]), "=r"(r[2]), "=r"(r[3]) : "r"(addr));
}

__device__ __forceinline__ void mma16816(float* c, const uint32_t* a, const uint32_t* b) {
    asm volatile(
        "mma.sync.aligned.m16n8k16.row.col.f32.bf16.bf16.f32 "
        "{%0,%1,%2,%3}, {%4,%5,%6,%7}, {%8,%9}, {%0,%1,%2,%3};"
        : "+f"(c[0]), "+f"(c[1]), "+f"(c[2]), "+f"(c[3])
        : "r"(a[0]), "r"(a[1]), "r"(a[2]), "r"(a[3]), "r"(b[0]), "r"(b[1]));
}

// ---------------- standalone Gaussian expansions (division-free) ----------------
// bond: thread = (v, j); 40 consecutive s outputs -> 80B-aligned stores
__global__ void expand_bond(const float* __restrict__ bond) {
    int idx = blockIdx.x * blockDim.x + threadIdx.x;
    if (idx >= NN * NEIGH) return;
    int v = idx / NEIGH, j = idx - v * NEIGH;
    float d = bond[idx];
    uint32_t hw[20], lw[20];
#pragma unroll
    for (int i = 0; i < 20; i++) {
        uint32_t h2 = 0, l2 = 0;
#pragma unroll
        for (int q = 0; q < 2; q++) {
            float t = d - (float)(2 * i + q) * (8.0f / 39.0f);
            float x = __expf(-t * t * 25.0f);
            __nv_bfloat16 hb = __float2bfloat16(x);
            __nv_bfloat16 lb = __float2bfloat16(x - __bfloat162float(hb));
            h2 |= (uint32_t)__bfloat16_as_ushort(hb) << (16 * q);
            l2 |= (uint32_t)__bfloat16_as_ushort(lb) << (16 * q);
        }
        hw[i] = h2; lw[i] = l2;
    }
    size_t base = (size_t)v * INB + j * 40;
    uint4* ph = (uint4*)(g_Xh + base);
    uint4* pl = (uint4*)(g_Xl + base);
#pragma unroll
    for (int u = 0; u < 5; u++) {
        ph[u] = make_uint4(hw[4*u], hw[4*u+1], hw[4*u+2], hw[4*u+3]);
        pl[u] = make_uint4(lw[4*u], lw[4*u+1], lw[4*u+2], lw[4*u+3]);
    }
}

// angle: thread = (v, pair of jk); 2x20 outputs -> 80B-aligned stores
__global__ void expand_angle(const float* __restrict__ ang) {
    int idx = blockIdx.x * blockDim.x + threadIdx.x;
    if (idx >= NN * 72) return;
    int v = idx / 72, p = idx - v * 72;
    float d0 = ang[(size_t)v * 144 + 2 * p];
    float d1 = ang[(size_t)v * 144 + 2 * p + 1];
    uint32_t hw[20], lw[20];
#pragma unroll
    for (int half = 0; half < 2; half++) {
        float d = half ? d1 : d0;
#pragma unroll
        for (int i = 0; i < 10; i++) {
            uint32_t h2 = 0, l2 = 0;
#pragma unroll
            for (int q = 0; q < 2; q++) {
                float t = d - (-1.0f + (float)(2 * i + q) * (2.0f / 19.0f));
                float x = __expf(-t * t * 100.0f);
                __nv_bfloat16 hb = __float2bfloat16(x);
                __nv_bfloat16 lb = __float2bfloat16(x - __bfloat162float(hb));
                h2 |= (uint32_t)__bfloat16_as_ushort(hb) << (16 * q);
                l2 |= (uint32_t)__bfloat16_as_ushort(lb) << (16 * q);
            }
            hw[half * 10 + i] = h2; lw[half * 10 + i] = l2;
        }
    }
    size_t base = (size_t)v * INA + p * 40;
    uint4* ph = (uint4*)(g_Xh + base);
    uint4* pl = (uint4*)(g_Xl + base);
#pragma unroll
    for (int u = 0; u < 5; u++) {
        ph[u] = make_uint4(hw[4*u], hw[4*u+1], hw[4*u+2], hw[4*u+3]);
        pl[u] = make_uint4(lw[4*u], lw[4*u+1], lw[4*u+2], lw[4*u+3]);
    }
}

// ---------------- GEMM: g_H[M,256] = X[M,K] @ Wt[256,K]^T (bf16x3) -------------
// Pure load->ldmatrix->MMA loop. CTA 128x128, 256 thr, 2 CTAs/SM, grid (157,2).
#define SM_AH 0
#define SM_AL 10240
#define SM_BH 20480
#define SM_BL 30720
#define STAGE 40960
#define SMEM_GEMM (2 * STAGE)

__device__ __forceinline__ void loadB_bf(uint32_t sb, int c,
                                         const __nv_bfloat16* Bh,
                                         const __nv_bfloat16* Bl,
                                         int K, int n0, int tid) {
#pragma unroll
    for (int q = 0; q < 4; q++) {
        int idx = tid + q * 256;
        int plane = idx >> 9;
        int rem = idx & 511;
        int row = rem >> 2, cc = rem & 3;
        const __nv_bfloat16* src = (plane ? Bl : Bh) +
                                   (size_t)(n0 + row) * K + c * 32 + cc * 8;
        uint32_t dst = sb + (plane ? SM_BL : SM_BH) + (uint32_t)(row * 80 + cc * 16);
        cp16(dst, src, 16);
    }
}

__device__ __forceinline__ void loadA_bf(uint32_t sb, int c,
                                         const __nv_bfloat16* Ah,
                                         const __nv_bfloat16* Al,
                                         int K, int m0, int tid) {
#pragma unroll
    for (int q = 0; q < 2; q++) {
        int j = tid + q * 256;
        int row = j >> 2, cc = j & 3;
        uint32_t doff = (uint32_t)(row * 80 + cc * 16);
        int gm = m0 + row;
        int gmc = gm < NN ? gm : 0;
        int sz = gm < NN ? 16 : 0;
        size_t aoff = (size_t)gmc * K + c * 32 + cc * 8;
        cp16(sb + SM_AH + doff, Ah + aoff, sz);
        cp16(sb + SM_AL + doff, Al + aoff, sz);
    }
}

__global__ __launch_bounds__(256, 2)
void gemm_mma(const __nv_bfloat16* __restrict__ Ah,
              const __nv_bfloat16* __restrict__ Al,
              const __nv_bfloat16* __restrict__ Bh,
              const __nv_bfloat16* __restrict__ Bl,
              int K) {
    extern __shared__ char smem[];
    uint32_t sbase = smem_u32(smem);
    int tid = threadIdx.x;
    int w = tid >> 5, l = tid & 31;
    int m0 = blockIdx.x * 128;
    int n0 = blockIdx.y * 128;
    int warp_m = (w >> 1) * 32;
    int warp_n = (w & 1) * 64;
    int nchunks = K >> 5;

    float acc[2][8][4];
#pragma unroll
    for (int i = 0; i < 2; i++)
#pragma unroll
        for (int j = 0; j < 8; j++)
#pragma unroll
            for (int q = 0; q < 4; q++) acc[i][j][q] = 0.f;

    uint32_t a_off[2];
#pragma unroll
    for (int mt = 0; mt < 2; mt++)
        a_off[mt] = (uint32_t)((warp_m + mt * 16 + (l & 15)) * 80 + ((l >> 4) * 16));
    uint32_t b_base = (uint32_t)((warp_n + (l & 7) + ((l >> 4) << 3)) * 80 +
                                 (((l >> 3) & 1) * 16));

    loadB_bf(sbase, 0, Bh, Bl, K, n0, tid);
    loadA_bf(sbase, 0, Ah, Al, K, m0, tid);
    asm volatile("cp.async.commit_group;" ::: "memory");

    for (int c = 0; c < nchunks; c++) {
        if (c + 1 < nchunks) {
            int st = (c + 1) & 1;
            uint32_t sb = sbase + st * STAGE;
            loadB_bf(sb, c + 1, Bh, Bl, K, n0, tid);
            loadA_bf(sb, c + 1, Ah, Al, K, m0, tid);
            asm volatile("cp.async.commit_group;" ::: "memory");
            asm volatile("cp.async.wait_group 1;" ::: "memory");
        } else {
            asm volatile("cp.async.wait_group 0;" ::: "memory");
        }
        __syncthreads();

        uint32_t sb = sbase + (uint32_t)((c & 1) * STAGE);
#pragma unroll
        for (int s = 0; s < 2; s++) {
            uint32_t af[2][2][4];
#pragma unroll
            for (int mt = 0; mt < 2; mt++) {
                ldmx4(af[mt][0], sb + SM_AH + a_off[mt] + s * 32);
                ldmx4(af[mt][1], sb + SM_AL + a_off[mt] + s * 32);
            }
            // pass-major issue order: same-acc MMAs >= 8 apart
#pragma unroll
            for (int pp = 0; pp < 2; pp++) {
                uint32_t bh[2][4], bl[2][4];
#pragma unroll
                for (int pi = 0; pi < 2; pi++) {
                    uint32_t ba = sb + b_base + (uint32_t)((2 * pp + pi) * 1280) + s * 32;
                    ldmx4(bh[pi], SM_BH + ba);
                    ldmx4(bl[pi], SM_BL + ba);
                }
#pragma unroll
                for (int pass = 0; pass < 3; pass++) {
#pragma unroll
                    for (int pi = 0; pi < 2; pi++) {
                        int p = 2 * pp + pi;
#pragma unroll
                        for (int mt = 0; mt < 2; mt++) {
                            const uint32_t* aa = (pass == 2) ? af[mt][1] : af[mt][0];
                            const uint32_t* bb = (pass == 1) ? bl[pi] : bh[pi];
                            mma16816(acc[mt][2 * p],     aa, bb);
                            mma16816(acc[mt][2 * p + 1], aa, bb + 2);
                        }
                    }
                }
            }
        }
        __syncthreads();
    }

#pragma unroll
    for (int mt = 0; mt < 2; mt++) {
        int m1 = m0 + warp_m + mt * 16 + (l >> 2);
        int m2 = m1 + 8;
#pragma unroll
        for (int nt = 0; nt < 8; nt++) {
            int nc = n0 + warp_n + nt * 8 + 2 * (l & 3);
            if (m1 < NN)
                *(float2*)(g_H + (size_t)m1 * 256 + nc) =
                    make_float2(acc[mt][nt][0], acc[mt][nt][1]);
            if (m2 < NN)
                *(float2*)(g_H + (size_t)m2 * 256 + nc) =
                    make_float2(acc[mt][nt][2], acc[mt][nt][3]);
        }
    }
}

// ---------------- weight transpose + bf16 split --------------------------------
__global__ void prep_wT(const float* __restrict__ Wroot,
                        const float* __restrict__ Wrel, int K) {
    __shared__ float sm[32][65];
    int tid = threadIdx.x;
    int k0 = blockIdx.x * 32;
    int cb = blockIdx.y;
#pragma unroll
    for (int i = 0; i < 8; i++) {
        int e = tid + i * 256;
        int k = e >> 6, h = e & 63;
        float wv = (cb == 0) ? Wroot[(size_t)(k0 + k) * 64 + h]
                             : Wrel[(size_t)(cb - 1) * K * 64 + (size_t)(k0 + k) * 64 + h];
        sm[k][h] = wv;
    }
    __syncthreads();
#pragma unroll
    for (int i = 0; i < 8; i++) {
        int e = tid + i * 256;
        int h = e >> 5, kk = e & 31;
        float wv = sm[kk][h];
        __nv_bfloat16 hi = __float2bfloat16(wv);
        float lo = wv - __bfloat162float(hi);
        size_t o = (size_t)(cb * 64 + h) * K + k0 + kk;
        g_Wth[o] = hi;
        g_Wtl[o] = __float2bfloat16(lo);
    }
}

// ---------------- graph preprocessing ------------------------------------------
__global__ void zero_kernel() {
    int i = blockIdx.x * blockDim.x + threadIdx.x;
    if (i < NN * 3) g_cnt[i] = 0;
    if (i < NN) g_deg[i] = 0;
    if (i < NCRYS * 128) g_pool[i] = 0.f;
}

__global__ void count_kernel(const int* __restrict__ nbr,
                             const int* __restrict__ species) {
    int e = blockIdx.x * blockDim.x + threadIdx.x;
    if (e >= EE) return;
    int src = e / NEIGH;
    int dst = nbr[e];
    int et = species[src] + species[dst];
    atomicAdd(&g_cnt[dst * 3 + et], 1);
    atomicAdd(&g_deg[dst], 1);
}

__global__ void scan_kernel() {
    __shared__ int ps[1024];
    int t = threadIdx.x;
    int base = t * 20;
    int local[20];
    int s = 0;
#pragma unroll
    for (int i = 0; i < 20; i++) {
        int idx = base + i;
        int d = (idx < NN) ? g_deg[idx] : 0;
        local[i] = s;
        s += d;
    }
    ps[t] = s;
    __syncthreads();
    for (int off = 1; off < 1024; off <<= 1) {
        int v = (t >= off) ? ps[t - off] : 0;
        __syncthreads();
        ps[t] += v;
        __syncthreads();
    }
    int pre = (t > 0) ? ps[t - 1] : 0;
#pragma unroll
    for (int i = 0; i < 20; i++) {
        int idx = base + i;
        if (idx < NN) {
            g_off[idx] = pre + local[i];
            g_pos[idx] = pre + local[i];
        }
    }
    if (t == 1023) g_off[NN] = ps[1023];
}

__global__ void fill_kernel(const int* __restrict__ nbr,
                            const int* __restrict__ species) {
    int e = blockIdx.x * blockDim.x + threadIdx.x;
    if (e >= EE) return;
    int src = e / NEIGH;
    int dst = nbr[e];
    int et = species[src] + species[dst];
    int p = atomicAdd(&g_pos[dst], 1);
    g_rev[p] = (src << 2) | et;
}

// ---------------- gather aggregation --------------------------------------------
template<int OUT>
__global__ void gather_kernel(const float* __restrict__ bias,
                              __nv_bfloat16* __restrict__ oh,
                              __nv_bfloat16* __restrict__ ol,
                              float* __restrict__ of) {
    int tid = threadIdx.x;
    int dst = blockIdx.x * 4 + (tid >> 6);
    int h = tid & 63;
    if (dst >= NN) return;
    int c0 = g_cnt[dst * 3 + 0], c1 = g_cnt[dst * 3 + 1], c2 = g_cnt[dst * 3 + 2];
    float inv0 = 1.0f / (float)(c0 > 0 ? c0 : 1);
    float inv1 = 1.0f / (float)(c1 > 0 ? c1 : 1);
    float inv2 = 1.0f / (float)(c2 > 0 ? c2 : 1);
    float v = g_H[(size_t)dst * 256 + h] + bias[h];
    int b0 = g_off[dst], b1 = g_off[dst + 1];
    for (int p = b0; p < b1; p++) {
        int pk = g_rev[p];
        int src = pk >> 2, et = pk & 3;
        float ic = (et == 0) ? inv0 : ((et == 1) ? inv1 : inv2);
        v += g_H[(size_t)src * 256 + (et + 1) * 64 + h] * ic;
    }
    v = v > 0.f ? v : 0.f;
    if (OUT == 0) {
        __nv_bfloat16 hi = __float2bfloat16(v);
        oh[dst * 64 + h] = hi;
        ol[dst * 64 + h] = __float2bfloat16(v - __bfloat162float(hi));
    } else {
        of[dst * 64 + h] = v;
    }
}

// ---------------- pooling + FC ---------------------------------------------------
#define POOL_NODES 160
__global__ void pool_kernel(const int* __restrict__ crys) {
    __shared__ int starts[NCRYS];
    int t = threadIdx.x;
    if (t < NCRYS) starts[t] = crys[t * 2];
    __syncthreads();
    int v0 = blockIdx.x * POOL_NODES;
    int v1 = v0 + POOL_NODES;
    if (v1 > NN) v1 = NN;
    const float* srcbuf = (t < 64) ? g_bf : g_af;
    int h = t & 63;
    float sum = 0.f;
    int cur = -2;
    for (int v = v0; v < v1; v++) {
        int c = 0;
#pragma unroll
        for (int k = 1; k < NCRYS; k++)
            if (starts[k] <= v) c = k;
        if (c != cur) {
            if (cur >= 0) atomicAdd(&g_pool[cur * 128 + t], sum);
            sum = 0.f;
            cur = c;
        }
        sum += srcbuf[v * 64 + h];
    }
    if (cur >= 0) atomicAdd(&g_pool[cur * 128 + t], sum);
}

__global__ void fc_kernel(const int* __restrict__ crys,
                          const float* __restrict__ W,
                          const float* __restrict__ b,
                          float* __restrict__ out) {
    int t = threadIdx.x;
    if (t >= NCRYS * 2) return;
    int c = t >> 1, o = t & 1;
    float cnt = (float)(crys[c * 2 + 1] - crys[c * 2]);
    float inv = 1.0f / cnt;
    float s = 0.f;
    for (int h = 0; h < 128; h++)
        s += g_pool[c * 128 + h] * inv * W[h * 2 + o];
    out[t] = s + b[o];
}

// ---------------- launch ----------------------------------------------------------
extern "C" void kernel_launch(void* const* d_in, const int* in_sizes, int n_in,
                              void* d_out, int out_size) {
    const float* bond     = (const float*)d_in[0];
    const float* angle    = (const float*)d_in[1];
    const int*   species  = (const int*)d_in[2];
    const int*   nbr      = (const int*)d_in[3];
    const int*   crys     = (const int*)d_in[4];
    const float* W1b_rel  = (const float*)d_in[5];
    const float* W1b_root = (const float*)d_in[6];
    const float* b1b      = (const float*)d_in[7];
    const float* W1a_rel  = (const float*)d_in[8];
    const float* W1a_root = (const float*)d_in[9];
    const float* b1a      = (const float*)d_in[10];
    const float* W2b_rel  = (const float*)d_in[11];
    const float* W2b_root = (const float*)d_in[12];
    const float* b2b      = (const float*)d_in[13];
    const float* W2a_rel  = (const float*)d_in[14];
    const float* W2a_root = (const float*)d_in[15];
    const float* b2a      = (const float*)d_in[16];
    const float* fcW      = (const float*)d_in[17];
    const float* fcb      = (const float*)d_in[18];
    float* out = (float*)d_out;

    cudaFuncSetAttribute(gemm_mma, cudaFuncAttributeMaxDynamicSharedMemorySize, SMEM_GEMM);

    __nv_bfloat16 *Xh, *Xl, *Wth, *Wtl, *bfh, *bfl, *afh, *afl;
    float *bfp, *afp;
    cudaGetSymbolAddress((void**)&Xh,  g_Xh);
    cudaGetSymbolAddress((void**)&Xl,  g_Xl);
    cudaGetSymbolAddress((void**)&Wth, g_Wth);
    cudaGetSymbolAddress((void**)&Wtl, g_Wtl);
    cudaGetSymbolAddress((void**)&bfh, g_bfh);
    cudaGetSymbolAddress((void**)&bfl, g_bfl);
    cudaGetSymbolAddress((void**)&afh, g_afh);
    cudaGetSymbolAddress((void**)&afl, g_afl);
    cudaGetSymbolAddress((void**)&bfp, g_bf);
    cudaGetSymbolAddress((void**)&afp, g_af);

    const int T = 256;
    dim3 ggrid((NN + 127) / 128, 2);   // (157, 2) -> 2 CTAs/SM
    const int GGRID = (NN + 3) / 4;

    // slot 3 = angle GEMM (profiled)
    zero_kernel<<<(NN * 3 + T - 1) / T, T>>>();                              // 0
    expand_angle<<<(NN * 72 + T - 1) / T, T>>>(angle);                       // 1
    prep_wT<<<dim3(INA / 32, 4), 256>>>(W1a_root, W1a_rel, INA);             // 2
    gemm_mma<<<ggrid, 256, SMEM_GEMM>>>(Xh, Xl, Wth, Wtl, INA);              // 3 <- profiled
    count_kernel<<<(EE + T - 1) / T, T>>>(nbr, species);
    scan_kernel<<<1, 1024>>>();
    fill_kernel<<<(EE + T - 1) / T, T>>>(nbr, species);
    gather_kernel<0><<<GGRID, 256>>>(b1a, afh, afl, nullptr);

    // --- bond, layer 1
    expand_bond<<<(NN * NEIGH + T - 1) / T, T>>>(bond);
    prep_wT<<<dim3(INB / 32, 4), 256>>>(W1b_root, W1b_rel, INB);
    gemm_mma<<<ggrid, 256, SMEM_GEMM>>>(Xh, Xl, Wth, Wtl, INB);
    gather_kernel<0><<<GGRID, 256>>>(b1b, bfh, bfl, nullptr);

    // --- bond, layer 2
    prep_wT<<<dim3(HD / 32, 4), 256>>>(W2b_root, W2b_rel, HD);
    gemm_mma<<<ggrid, 256, SMEM_GEMM>>>(bfh, bfl, Wth, Wtl, HD);
    gather_kernel<1><<<GGRID, 256>>>(b2b, nullptr, nullptr, bfp);

    // --- angle, layer 2
    prep_wT<<<dim3(HD / 32, 4), 256>>>(W2a_root, W2a_rel, HD);
    gemm_mma<<<ggrid, 256, SMEM_GEMM>>>(afh, afl, Wth, Wtl, HD);
    gather_kernel<1><<<GGRID, 256>>>(b2a, nullptr, nullptr, afp);

    // --- pooling + FC
    pool_kernel<<<(NN + POOL_NODES - 1) / POOL_NODES, 128>>>(crys);
    fc_kernel<<<1, 64>>>(crys, fcW, fcb, out);
}

// round 11
// speedup vs baseline: 2.8155x; 1.5026x over previous
#include <cuda_runtime.h>
#include <cuda_fp16.h>
#include <cstdint>

#define NN     20000
#define NEIGH  12
#define EE     (NN*NEIGH)
#define HD     64
#define INB    480
#define INA    2880
#define NCRYS  20

// ---------------- scratch ----------------------------------------------------
__device__ __align__(256) __half g_X[(size_t)NN * INA];     // fp16 activations
__device__ __align__(256) __half g_Wth[256 * INA];          // weight hi (x16)
__device__ __align__(256) __half g_Wtl[256 * INA];          // weight lo (x16)
__device__ float g_H[(size_t)NN * 256];
__device__ float g_bf[NN * HD];
__device__ float g_af[NN * HD];
__device__ __align__(256) __half g_bfx[NN * HD];
__device__ __align__(256) __half g_afx[NN * HD];
__device__ int   g_cnt[NN * 3];
__device__ int   g_deg[NN];
__device__ int   g_off[NN + 1];
__device__ int   g_pos[NN];
__device__ int   g_rev[EE];
__device__ float g_pool[NCRYS * 128];

// ---------------- helpers ------------------------------------------------------
__device__ __forceinline__ uint32_t smem_u32(const void* p) {
    uint32_t a;
    asm("{ .reg .u64 t; cvta.to.shared.u64 t, %1; cvt.u32.u64 %0, t; }"
        : "=r"(a) : "l"(p));
    return a;
}

__device__ __forceinline__ void cp16(uint32_t dst, const void* src, int sz) {
    asm volatile("cp.async.cg.shared.global [%0], [%1], 16, %2;"
                 :: "r"(dst), "l"(src), "r"(sz));
}

__device__ __forceinline__ void ldmx4(uint32_t* r, uint32_t addr) {
    asm volatile("ldmatrix.sync.aligned.m8n8.x4.shared.b16 {%0,%1,%2,%3}, [%4];"
                 : "=r"(r[0]), "=r"(r[1]), "=r"(r[2]), "=r"(r[3]) : "r"(addr));
}

__device__ __forceinline__ void mma16816(float* c, const uint32_t* a, const uint32_t* b) {
    asm volatile(
        "mma.sync.aligned.m16n8k16.row.col.f32.f16.f16.f32 "
        "{%0,%1,%2,%3}, {%4,%5,%6,%7}, {%8,%9}, {%0,%1,%2,%3};"
        : "+f"(c[0]), "+f"(c[1]), "+f"(c[2]), "+f"(c[3])
        : "r"(a[0]), "r"(a[1]), "r"(a[2]), "r"(a[3]), "r"(b[0]), "r"(b[1]));
}

// ---------------- standalone Gaussian expansions (fp16, division-free) ----------
__global__ void expand_bond(const float* __restrict__ bond) {
    int idx = blockIdx.x * blockDim.x + threadIdx.x;
    if (idx >= NN * NEIGH) return;
    int v = idx / NEIGH, j = idx - v * NEIGH;
    float d = bond[idx];
    uint32_t hw[20];
#pragma unroll
    for (int i = 0; i < 20; i++) {
        uint32_t h2 = 0;
#pragma unroll
        for (int q = 0; q < 2; q++) {
            float t = d - (float)(2 * i + q) * (8.0f / 39.0f);
            float x = __expf(-t * t * 25.0f);
            h2 |= (uint32_t)__half_as_ushort(__float2half_rn(x)) << (16 * q);
        }
        hw[i] = h2;
    }
    uint4* ph = (uint4*)(g_X + (size_t)v * INB + j * 40);
#pragma unroll
    for (int u = 0; u < 5; u++)
        ph[u] = make_uint4(hw[4*u], hw[4*u+1], hw[4*u+2], hw[4*u+3]);
}

__global__ void expand_angle(const float* __restrict__ ang) {
    int idx = blockIdx.x * blockDim.x + threadIdx.x;
    if (idx >= NN * 72) return;
    int v = idx / 72, p = idx - v * 72;
    float d0 = ang[(size_t)v * 144 + 2 * p];
    float d1 = ang[(size_t)v * 144 + 2 * p + 1];
    uint32_t hw[20];
#pragma unroll
    for (int half = 0; half < 2; half++) {
        float d = half ? d1 : d0;
#pragma unroll
        for (int i = 0; i < 10; i++) {
            uint32_t h2 = 0;
#pragma unroll
            for (int q = 0; q < 2; q++) {
                float t = d - (-1.0f + (float)(2 * i + q) * (2.0f / 19.0f));
                float x = __expf(-t * t * 100.0f);
                h2 |= (uint32_t)__half_as_ushort(__float2half_rn(x)) << (16 * q);
            }
            hw[half * 10 + i] = h2;
        }
    }
    uint4* ph = (uint4*)(g_X + (size_t)v * INA + p * 40);
#pragma unroll
    for (int u = 0; u < 5; u++)
        ph[u] = make_uint4(hw[4*u], hw[4*u+1], hw[4*u+2], hw[4*u+3]);
}

// ---------------- GEMM: g_H[M,256] = (X @ (Wh+Wl)^T) / 16  (fp16 x2) ----------
// CTA 128x128, 256 thr, 2 CTAs/SM, grid (157,2). K-chunk 32, 3-stage cp.async,
// ONE __syncthreads per chunk. smem rows 80B-padded (conflict-free ldmatrix).
#define SM_A  0
#define SM_BH 10240
#define SM_BL 20480
#define STAGE 30720
#define SMEM_GEMM (3 * STAGE)

__device__ __forceinline__ void loadB_h(uint32_t sb, int c,
                                        const __half* Bh, const __half* Bl,
                                        int K, int n0, int tid) {
#pragma unroll
    for (int q = 0; q < 4; q++) {
        int idx = tid + q * 256;            // 0..1023
        int plane = idx >> 9;
        int rem = idx & 511;
        int row = rem >> 2, cc = rem & 3;
        const __half* src = (plane ? Bl : Bh) +
                            (size_t)(n0 + row) * K + c * 32 + cc * 8;
        uint32_t dst = sb + (plane ? SM_BL : SM_BH) + (uint32_t)(row * 80 + cc * 16);
        cp16(dst, src, 16);
    }
}

__device__ __forceinline__ void loadA_h(uint32_t sb, int c,
                                        const __half* A,
                                        int K, int m0, int tid) {
#pragma unroll
    for (int q = 0; q < 2; q++) {
        int j = tid + q * 256;
        int row = j >> 2, cc = j & 3;
        uint32_t doff = (uint32_t)(row * 80 + cc * 16);
        int gm = m0 + row;
        int gmc = gm < NN ? gm : 0;
        int sz = gm < NN ? 16 : 0;
        cp16(sb + SM_A + doff, A + (size_t)gmc * K + c * 32 + cc * 8, sz);
    }
}

__global__ __launch_bounds__(256, 2)
void gemm_mma(const __half* __restrict__ A,
              const __half* __restrict__ Bh,
              const __half* __restrict__ Bl,
              int K) {
    extern __shared__ char smem[];
    uint32_t sbase = smem_u32(smem);
    int tid = threadIdx.x;
    int w = tid >> 5, l = tid & 31;
    int m0 = blockIdx.x * 128;
    int n0 = blockIdx.y * 128;
    int warp_m = (w >> 1) * 32;
    int warp_n = (w & 1) * 64;
    int nchunks = K >> 5;

    float acc[2][8][4];
#pragma unroll
    for (int i = 0; i < 2; i++)
#pragma unroll
        for (int j = 0; j < 8; j++)
#pragma unroll
            for (int q = 0; q < 4; q++) acc[i][j][q] = 0.f;

    uint32_t a_off[2];
#pragma unroll
    for (int mt = 0; mt < 2; mt++)
        a_off[mt] = (uint32_t)((warp_m + mt * 16 + (l & 15)) * 80 + ((l >> 4) * 16));
    uint32_t b_base = (uint32_t)((warp_n + (l & 7) + ((l >> 4) << 3)) * 80 +
                                 (((l >> 3) & 1) * 16));

    // prologue: stages 0,1
    loadB_h(sbase, 0, Bh, Bl, K, n0, tid);
    loadA_h(sbase, 0, A, K, m0, tid);
    asm volatile("cp.async.commit_group;" ::: "memory");
    if (nchunks > 1) {
        loadB_h(sbase + STAGE, 1, Bh, Bl, K, n0, tid);
        loadA_h(sbase + STAGE, 1, A, K, m0, tid);
        asm volatile("cp.async.commit_group;" ::: "memory");
    }

    int st = 0;
    for (int c = 0; c < nchunks; c++) {
        if (c == nchunks - 1)
            asm volatile("cp.async.wait_group 0;" ::: "memory");
        else
            asm volatile("cp.async.wait_group 1;" ::: "memory");
        __syncthreads();

        uint32_t sb = sbase + (uint32_t)(st * STAGE);
#pragma unroll
        for (int s = 0; s < 2; s++) {
            uint32_t af[2][4];
#pragma unroll
            for (int mt = 0; mt < 2; mt++)
                ldmx4(af[mt], sb + SM_A + a_off[mt] + s * 32);
#pragma unroll
            for (int pp = 0; pp < 2; pp++) {
                uint32_t bh[2][4], bl[2][4];
#pragma unroll
                for (int pi = 0; pi < 2; pi++) {
                    uint32_t ba = sb + b_base + (uint32_t)((2 * pp + pi) * 1280) + s * 32;
                    ldmx4(bh[pi], SM_BH + ba);
                    ldmx4(bl[pi], SM_BL + ba);
                }
#pragma unroll
                for (int pass = 0; pass < 2; pass++) {
#pragma unroll
                    for (int pi = 0; pi < 2; pi++) {
                        int p = 2 * pp + pi;
                        const uint32_t* bb = pass ? bl[pi] : bh[pi];
#pragma unroll
                        for (int mt = 0; mt < 2; mt++) {
                            mma16816(acc[mt][2 * p],     af[mt], bb);
                            mma16816(acc[mt][2 * p + 1], af[mt], bb + 2);
                        }
                    }
                }
            }
        }
        // issue loads for chunk c+2 into the stage just freed... (stage (st+2)%3)
        if (c + 2 < nchunks) {
            int st2 = (st + 2) % 3;
            uint32_t sb2 = sbase + (uint32_t)(st2 * STAGE);
            loadB_h(sb2, c + 2, Bh, Bl, K, n0, tid);
            loadA_h(sb2, c + 2, A, K, m0, tid);
            asm volatile("cp.async.commit_group;" ::: "memory");
        }
        st = (st + 1) % 3;
    }

    // epilogue: undo the x16 weight scaling
#pragma unroll
    for (int mt = 0; mt < 2; mt++) {
        int m1 = m0 + warp_m + mt * 16 + (l >> 2);
        int m2 = m1 + 8;
#pragma unroll
        for (int nt = 0; nt < 8; nt++) {
            int nc = n0 + warp_n + nt * 8 + 2 * (l & 3);
            if (m1 < NN)
                *(float2*)(g_H + (size_t)m1 * 256 + nc) =
                    make_float2(acc[mt][nt][0] * 0.0625f, acc[mt][nt][1] * 0.0625f);
            if (m2 < NN)
                *(float2*)(g_H + (size_t)m2 * 256 + nc) =
                    make_float2(acc[mt][nt][2] * 0.0625f, acc[mt][nt][3] * 0.0625f);
        }
    }
}

// ---------------- weight transpose + fp16 hi/lo split (x16 scaled) -------------
__global__ void prep_wT(const float* __restrict__ Wroot,
                        const float* __restrict__ Wrel, int K) {
    __shared__ float sm[32][65];
    int tid = threadIdx.x;
    int k0 = blockIdx.x * 32;
    int cb = blockIdx.y;
#pragma unroll
    for (int i = 0; i < 8; i++) {
        int e = tid + i * 256;
        int k = e >> 6, h = e & 63;
        float wv = (cb == 0) ? Wroot[(size_t)(k0 + k) * 64 + h]
                             : Wrel[(size_t)(cb - 1) * K * 64 + (size_t)(k0 + k) * 64 + h];
        sm[k][h] = wv * 16.0f;
    }
    __syncthreads();
#pragma unroll
    for (int i = 0; i < 8; i++) {
        int e = tid + i * 256;
        int h = e >> 5, kk = e & 31;
        float wv = sm[kk][h];
        __half hi = __float2half_rn(wv);
        __half lo = __float2half_rn(wv - __half2float(hi));
        size_t o = (size_t)(cb * 64 + h) * K + k0 + kk;
        g_Wth[o] = hi;
        g_Wtl[o] = lo;
    }
}

// ---------------- graph preprocessing ------------------------------------------
__global__ void zero_kernel() {
    int i = blockIdx.x * blockDim.x + threadIdx.x;
    if (i < NN * 3) g_cnt[i] = 0;
    if (i < NN) g_deg[i] = 0;
    if (i < NCRYS * 128) g_pool[i] = 0.f;
}

__global__ void count_kernel(const int* __restrict__ nbr,
                             const int* __restrict__ species) {
    int e = blockIdx.x * blockDim.x + threadIdx.x;
    if (e >= EE) return;
    int src = e / NEIGH;
    int dst = nbr[e];
    int et = species[src] + species[dst];
    atomicAdd(&g_cnt[dst * 3 + et], 1);
    atomicAdd(&g_deg[dst], 1);
}

__global__ void scan_kernel() {
    __shared__ int ps[1024];
    int t = threadIdx.x;
    int base = t * 20;
    int local[20];
    int s = 0;
#pragma unroll
    for (int i = 0; i < 20; i++) {
        int idx = base + i;
        int d = (idx < NN) ? g_deg[idx] : 0;
        local[i] = s;
        s += d;
    }
    ps[t] = s;
    __syncthreads();
    for (int off = 1; off < 1024; off <<= 1) {
        int v = (t >= off) ? ps[t - off] : 0;
        __syncthreads();
        ps[t] += v;
        __syncthreads();
    }
    int pre = (t > 0) ? ps[t - 1] : 0;
#pragma unroll
    for (int i = 0; i < 20; i++) {
        int idx = base + i;
        if (idx < NN) {
            g_off[idx] = pre + local[i];
            g_pos[idx] = pre + local[i];
        }
    }
    if (t == 1023) g_off[NN] = ps[1023];
}

__global__ void fill_kernel(const int* __restrict__ nbr,
                            const int* __restrict__ species) {
    int e = blockIdx.x * blockDim.x + threadIdx.x;
    if (e >= EE) return;
    int src = e / NEIGH;
    int dst = nbr[e];
    int et = species[src] + species[dst];
    int p = atomicAdd(&g_pos[dst], 1);
    g_rev[p] = (src << 2) | et;
}

// ---------------- gather aggregation --------------------------------------------
template<int OUT>
__global__ void gather_kernel(const float* __restrict__ bias,
                              __half* __restrict__ ox,
                              float* __restrict__ of) {
    int tid = threadIdx.x;
    int dst = blockIdx.x * 4 + (tid >> 6);
    int h = tid & 63;
    if (dst >= NN) return;
    int c0 = g_cnt[dst * 3 + 0], c1 = g_cnt[dst * 3 + 1], c2 = g_cnt[dst * 3 + 2];
    float inv0 = 1.0f / (float)(c0 > 0 ? c0 : 1);
    float inv1 = 1.0f / (float)(c1 > 0 ? c1 : 1);
    float inv2 = 1.0f / (float)(c2 > 0 ? c2 : 1);
    float v = g_H[(size_t)dst * 256 + h] + bias[h];
    int b0 = g_off[dst], b1 = g_off[dst + 1];
    for (int p = b0; p < b1; p++) {
        int pk = g_rev[p];
        int src = pk >> 2, et = pk & 3;
        float ic = (et == 0) ? inv0 : ((et == 1) ? inv1 : inv2);
        v += g_H[(size_t)src * 256 + (et + 1) * 64 + h] * ic;
    }
    v = v > 0.f ? v : 0.f;
    if (OUT == 0) ox[dst * 64 + h] = __float2half_rn(v);
    else          of[dst * 64 + h] = v;
}

// ---------------- pooling + FC ---------------------------------------------------
#define POOL_NODES 160
__global__ void pool_kernel(const int* __restrict__ crys) {
    __shared__ int starts[NCRYS];
    int t = threadIdx.x;
    if (t < NCRYS) starts[t] = crys[t * 2];
    __syncthreads();
    int v0 = blockIdx.x * POOL_NODES;
    int v1 = v0 + POOL_NODES;
    if (v1 > NN) v1 = NN;
    const float* srcbuf = (t < 64) ? g_bf : g_af;
    int h = t & 63;
    float sum = 0.f;
    int cur = -2;
    for (int v = v0; v < v1; v++) {
        int c = 0;
#pragma unroll
        for (int k = 1; k < NCRYS; k++)
            if (starts[k] <= v) c = k;
        if (c != cur) {
            if (cur >= 0) atomicAdd(&g_pool[cur * 128 + t], sum);
            sum = 0.f;
            cur = c;
        }
        sum += srcbuf[v * 64 + h];
    }
    if (cur >= 0) atomicAdd(&g_pool[cur * 128 + t], sum);
}

__global__ void fc_kernel(const int* __restrict__ crys,
                          const float* __restrict__ W,
                          const float* __restrict__ b,
                          float* __restrict__ out) {
    int t = threadIdx.x;
    if (t >= NCRYS * 2) return;
    int c = t >> 1, o = t & 1;
    float cnt = (float)(crys[c * 2 + 1] - crys[c * 2]);
    float inv = 1.0f / cnt;
    float s = 0.f;
    for (int h = 0; h < 128; h++)
        s += g_pool[c * 128 + h] * inv * W[h * 2 + o];
    out[t] = s + b[o];
}

// ---------------- launch ----------------------------------------------------------
extern "C" void kernel_launch(void* const* d_in, const int* in_sizes, int n_in,
                              void* d_out, int out_size) {
    const float* bond     = (const float*)d_in[0];
    const float* angle    = (const float*)d_in[1];
    const int*   species  = (const int*)d_in[2];
    const int*   nbr      = (const int*)d_in[3];
    const int*   crys     = (const int*)d_in[4];
    const float* W1b_rel  = (const float*)d_in[5];
    const float* W1b_root = (const float*)d_in[6];
    const float* b1b      = (const float*)d_in[7];
    const float* W1a_rel  = (const float*)d_in[8];
    const float* W1a_root = (const float*)d_in[9];
    const float* b1a      = (const float*)d_in[10];
    const float* W2b_rel  = (const float*)d_in[11];
    const float* W2b_root = (const float*)d_in[12];
    const float* b2b      = (const float*)d_in[13];
    const float* W2a_rel  = (const float*)d_in[14];
    const float* W2a_root = (const float*)d_in[15];
    const float* b2a      = (const float*)d_in[16];
    const float* fcW      = (const float*)d_in[17];
    const float* fcb      = (const float*)d_in[18];
    float* out = (float*)d_out;

    cudaFuncSetAttribute(gemm_mma, cudaFuncAttributeMaxDynamicSharedMemorySize, SMEM_GEMM);

    __half *X, *Wth, *Wtl, *bfx, *afx;
    float *bfp, *afp;
    cudaGetSymbolAddress((void**)&X,   g_X);
    cudaGetSymbolAddress((void**)&Wth, g_Wth);
    cudaGetSymbolAddress((void**)&Wtl, g_Wtl);
    cudaGetSymbolAddress((void**)&bfx, g_bfx);
    cudaGetSymbolAddress((void**)&afx, g_afx);
    cudaGetSymbolAddress((void**)&bfp, g_bf);
    cudaGetSymbolAddress((void**)&afp, g_af);

    const int T = 256;
    dim3 ggrid((NN + 127) / 128, 2);   // (157, 2) -> 2 CTAs/SM
    const int GGRID = (NN + 3) / 4;

    // slot 3 = angle GEMM (profiled)
    zero_kernel<<<(NN * 3 + T - 1) / T, T>>>();                              // 0
    expand_angle<<<(NN * 72 + T - 1) / T, T>>>(angle);                       // 1
    prep_wT<<<dim3(INA / 32, 4), 256>>>(W1a_root, W1a_rel, INA);             // 2
    gemm_mma<<<ggrid, 256, SMEM_GEMM>>>(X, Wth, Wtl, INA);                   // 3 <- profiled
    count_kernel<<<(EE + T - 1) / T, T>>>(nbr, species);
    scan_kernel<<<1, 1024>>>();
    fill_kernel<<<(EE + T - 1) / T, T>>>(nbr, species);
    gather_kernel<0><<<GGRID, 256>>>(b1a, afx, nullptr);

    // --- bond, layer 1
    expand_bond<<<(NN * NEIGH + T - 1) / T, T>>>(bond);
    prep_wT<<<dim3(INB / 32, 4), 256>>>(W1b_root, W1b_rel, INB);
    gemm_mma<<<ggrid, 256, SMEM_GEMM>>>(X, Wth, Wtl, INB);
    gather_kernel<0><<<GGRID, 256>>>(b1b, bfx, nullptr);

    // --- bond, layer 2
    prep_wT<<<dim3(HD / 32, 4), 256>>>(W2b_root, W2b_rel, HD);
    gemm_mma<<<ggrid, 256, SMEM_GEMM>>>(bfx, Wth, Wtl, HD);
    gather_kernel<1><<<GGRID, 256>>>(b2b, nullptr, bfp);

    // --- angle, layer 2
    prep_wT<<<dim3(HD / 32, 4), 256>>>(W2a_root, W2a_rel, HD);
    gemm_mma<<<ggrid, 256, SMEM_GEMM>>>(afx, Wth, Wtl, HD);
    gather_kernel<1><<<GGRID, 256>>>(b2a, nullptr, afp);

    // --- pooling + FC
    pool_kernel<<<(NN + POOL_NODES - 1) / POOL_NODES, 128>>>(crys);
    fc_kernel<<<1, 64>>>(crys, fcW, fcb, out);
}

// round 12
// speedup vs baseline: 3.5019x; 1.2438x over previous
#include <cuda_runtime.h>
#include <cuda_fp16.h>
#include <cstdint>

#define NN     20000
#define NEIGH  12
#define EE     (NN*NEIGH)
#define HD     64
#define INB    480
#define INA    2880
#define NCRYS  20

// ---------------- scratch ----------------------------------------------------
__device__ __align__(256) __half g_X[(size_t)NN * INA];     // fp16 activations
__device__ __align__(256) __half g_Wt[256 * INA];           // fp16 weights [256,K]
__device__ float g_H[(size_t)NN * 256];
__device__ float g_bf[NN * HD];
__device__ float g_af[NN * HD];
__device__ __align__(256) __half g_bfx[NN * HD];
__device__ __align__(256) __half g_afx[NN * HD];
__device__ int   g_cnt[NN * 3];
__device__ int   g_deg[NN];
__device__ int   g_off[NN + 1];
__device__ int   g_pos[NN];
__device__ int   g_rev[EE];
__device__ float g_pool[NCRYS * 128];

// ---------------- helpers ------------------------------------------------------
__device__ __forceinline__ uint32_t smem_u32(const void* p) {
    uint32_t a;
    asm("{ .reg .u64 t; cvta.to.shared.u64 t, %1; cvt.u32.u64 %0, t; }"
        : "=r"(a) : "l"(p));
    return a;
}

__device__ __forceinline__ void cp16(uint32_t dst, const void* src, int sz) {
    asm volatile("cp.async.cg.shared.global [%0], [%1], 16, %2;"
                 :: "r"(dst), "l"(src), "r"(sz));
}

__device__ __forceinline__ void ldmx4(uint32_t* r, uint32_t addr) {
    asm volatile("ldmatrix.sync.aligned.m8n8.x4.shared.b16 {%0,%1,%2,%3}, [%4];"
                 : "=r"(r[0]), "=r"(r[1]), "=r"(r[2]), "=r"(r[3]) : "r"(addr));
}

__device__ __forceinline__ void mma16816(float* c, const uint32_t* a, const uint32_t* b) {
    asm volatile(
        "mma.sync.aligned.m16n8k16.row.col.f32.f16.f16.f32 "
        "{%0,%1,%2,%3}, {%4,%5,%6,%7}, {%8,%9}, {%0,%1,%2,%3};"
        : "+f"(c[0]), "+f"(c[1]), "+f"(c[2]), "+f"(c[3])
        : "r"(a[0]), "r"(a[1]), "r"(a[2]), "r"(a[3]), "r"(b[0]), "r"(b[1]));
}

// ---------------- standalone Gaussian expansions (fp16, division-free) ----------
__global__ void expand_bond(const float* __restrict__ bond) {
    int idx = blockIdx.x * blockDim.x + threadIdx.x;
    if (idx >= NN * NEIGH) return;
    int v = idx / NEIGH, j = idx - v * NEIGH;
    float d = bond[idx];
    uint32_t hw[20];
#pragma unroll
    for (int i = 0; i < 20; i++) {
        uint32_t h2 = 0;
#pragma unroll
        for (int q = 0; q < 2; q++) {
            float t = d - (float)(2 * i + q) * (8.0f / 39.0f);
            float x = __expf(-t * t * 25.0f);
            h2 |= (uint32_t)__half_as_ushort(__float2half_rn(x)) << (16 * q);
        }
        hw[i] = h2;
    }
    uint4* ph = (uint4*)(g_X + (size_t)v * INB + j * 40);
#pragma unroll
    for (int u = 0; u < 5; u++)
        ph[u] = make_uint4(hw[4*u], hw[4*u+1], hw[4*u+2], hw[4*u+3]);
}

__global__ void expand_angle(const float* __restrict__ ang) {
    int idx = blockIdx.x * blockDim.x + threadIdx.x;
    if (idx >= NN * 72) return;
    int v = idx / 72, p = idx - v * 72;
    float d0 = ang[(size_t)v * 144 + 2 * p];
    float d1 = ang[(size_t)v * 144 + 2 * p + 1];
    uint32_t hw[20];
#pragma unroll
    for (int half = 0; half < 2; half++) {
        float d = half ? d1 : d0;
#pragma unroll
        for (int i = 0; i < 10; i++) {
            uint32_t h2 = 0;
#pragma unroll
            for (int q = 0; q < 2; q++) {
                float t = d - (-1.0f + (float)(2 * i + q) * (2.0f / 19.0f));
                float x = __expf(-t * t * 100.0f);
                h2 |= (uint32_t)__half_as_ushort(__float2half_rn(x)) << (16 * q);
            }
            hw[half * 10 + i] = h2;
        }
    }
    uint4* ph = (uint4*)(g_X + (size_t)v * INA + p * 40);
#pragma unroll
    for (int u = 0; u < 5; u++)
        ph[u] = make_uint4(hw[4*u], hw[4*u+1], hw[4*u+2], hw[4*u+3]);
}

// ---------------- GEMM: g_H[M,256] = X @ W^T  (single fp16 pass) ---------------
// CTA 128x128, 256 thr, 2 CTAs/SM, grid (157,2). K-chunk 32, 4-stage cp.async,
// one __syncthreads per chunk. smem rows 80B-padded (conflict-free ldmatrix).
#define SM_A  0
#define SM_B  10240
#define STAGE 20480
#define SMEM_GEMM (4 * STAGE)

__device__ __forceinline__ void load_chunk(uint32_t sb, int c,
                                           const __half* A, const __half* B,
                                           int K, int m0, int n0, int tid) {
#pragma unroll
    for (int q = 0; q < 2; q++) {
        int j = tid + q * 256;
        int row = j >> 2, cc = j & 3;
        uint32_t doff = (uint32_t)(row * 80 + cc * 16);
        // A
        int gm = m0 + row;
        int gmc = gm < NN ? gm : 0;
        int sz = gm < NN ? 16 : 0;
        cp16(sb + SM_A + doff, A + (size_t)gmc * K + c * 32 + cc * 8, sz);
        // B
        cp16(sb + SM_B + doff, B + (size_t)(n0 + row) * K + c * 32 + cc * 8, 16);
    }
    asm volatile("cp.async.commit_group;" ::: "memory");
}

__global__ __launch_bounds__(256, 2)
void gemm_mma(const __half* __restrict__ A,
              const __half* __restrict__ B,
              int K) {
    extern __shared__ char smem[];
    uint32_t sbase = smem_u32(smem);
    int tid = threadIdx.x;
    int w = tid >> 5, l = tid & 31;
    int m0 = blockIdx.x * 128;
    int n0 = blockIdx.y * 128;
    int warp_m = (w >> 1) * 32;
    int warp_n = (w & 1) * 64;
    int nchunks = K >> 5;

    float acc[2][8][4];
#pragma unroll
    for (int i = 0; i < 2; i++)
#pragma unroll
        for (int j = 0; j < 8; j++)
#pragma unroll
            for (int q = 0; q < 4; q++) acc[i][j][q] = 0.f;

    uint32_t a_off[2];
#pragma unroll
    for (int mt = 0; mt < 2; mt++)
        a_off[mt] = (uint32_t)((warp_m + mt * 16 + (l & 15)) * 80 + ((l >> 4) * 16));
    uint32_t b_base = (uint32_t)((warp_n + (l & 7) + ((l >> 4) << 3)) * 80 +
                                 (((l >> 3) & 1) * 16));

    // prologue: up to 3 stages ahead
    load_chunk(sbase, 0, A, B, K, m0, n0, tid);
    if (nchunks > 1) load_chunk(sbase + STAGE, 1, A, B, K, m0, n0, tid);
    if (nchunks > 2) load_chunk(sbase + 2 * STAGE, 2, A, B, K, m0, n0, tid);

    int st = 0;
    for (int c = 0; c < nchunks; c++) {
        int rem = nchunks - 1 - c;
        if (rem >= 2)      asm volatile("cp.async.wait_group 2;" ::: "memory");
        else if (rem == 1) asm volatile("cp.async.wait_group 1;" ::: "memory");
        else               asm volatile("cp.async.wait_group 0;" ::: "memory");
        __syncthreads();

        uint32_t sb = sbase + (uint32_t)(st * STAGE);
#pragma unroll
        for (int s = 0; s < 2; s++) {
            uint32_t af[2][4];
#pragma unroll
            for (int mt = 0; mt < 2; mt++)
                ldmx4(af[mt], sb + SM_A + a_off[mt] + s * 32);
#pragma unroll
            for (int p = 0; p < 4; p++) {
                uint32_t rb[4];
                ldmx4(rb, sb + SM_B + b_base + (uint32_t)(p * 1280) + s * 32);
#pragma unroll
                for (int mt = 0; mt < 2; mt++) {
                    mma16816(acc[mt][2 * p],     af[mt], rb);
                    mma16816(acc[mt][2 * p + 1], af[mt], rb + 2);
                }
            }
        }
        if (c + 3 < nchunks) {
            int st3 = (st + 3) & 3;
            load_chunk(sbase + (uint32_t)(st3 * STAGE), c + 3, A, B, K, m0, n0, tid);
        }
        st = (st + 1) & 3;
    }

#pragma unroll
    for (int mt = 0; mt < 2; mt++) {
        int m1 = m0 + warp_m + mt * 16 + (l >> 2);
        int m2 = m1 + 8;
#pragma unroll
        for (int nt = 0; nt < 8; nt++) {
            int nc = n0 + warp_n + nt * 8 + 2 * (l & 3);
            if (m1 < NN)
                *(float2*)(g_H + (size_t)m1 * 256 + nc) =
                    make_float2(acc[mt][nt][0], acc[mt][nt][1]);
            if (m2 < NN)
                *(float2*)(g_H + (size_t)m2 * 256 + nc) =
                    make_float2(acc[mt][nt][2], acc[mt][nt][3]);
        }
    }
}

// ---------------- weight transpose + fp16 convert ------------------------------
__global__ void prep_wT(const float* __restrict__ Wroot,
                        const float* __restrict__ Wrel, int K) {
    __shared__ float sm[32][65];
    int tid = threadIdx.x;
    int k0 = blockIdx.x * 32;
    int cb = blockIdx.y;
#pragma unroll
    for (int i = 0; i < 8; i++) {
        int e = tid + i * 256;
        int k = e >> 6, h = e & 63;
        float wv = (cb == 0) ? Wroot[(size_t)(k0 + k) * 64 + h]
                             : Wrel[(size_t)(cb - 1) * K * 64 + (size_t)(k0 + k) * 64 + h];
        sm[k][h] = wv;
    }
    __syncthreads();
#pragma unroll
    for (int i = 0; i < 8; i++) {
        int e = tid + i * 256;
        int h = e >> 5, kk = e & 31;
        g_Wt[(size_t)(cb * 64 + h) * K + k0 + kk] = __float2half_rn(sm[kk][h]);
    }
}

// ---------------- graph preprocessing ------------------------------------------
__global__ void zero_kernel() {
    int i = blockIdx.x * blockDim.x + threadIdx.x;
    if (i < NN * 3) g_cnt[i] = 0;
    if (i < NN) g_deg[i] = 0;
    if (i < NCRYS * 128) g_pool[i] = 0.f;
}

__global__ void count_kernel(const int* __restrict__ nbr,
                             const int* __restrict__ species) {
    int e = blockIdx.x * blockDim.x + threadIdx.x;
    if (e >= EE) return;
    int src = e / NEIGH;
    int dst = nbr[e];
    int et = species[src] + species[dst];
    atomicAdd(&g_cnt[dst * 3 + et], 1);
    atomicAdd(&g_deg[dst], 1);
}

__global__ void scan_kernel() {
    __shared__ int ps[1024];
    int t = threadIdx.x;
    int base = t * 20;
    int local[20];
    int s = 0;
#pragma unroll
    for (int i = 0; i < 20; i++) {
        int idx = base + i;
        int d = (idx < NN) ? g_deg[idx] : 0;
        local[i] = s;
        s += d;
    }
    ps[t] = s;
    __syncthreads();
    for (int off = 1; off < 1024; off <<= 1) {
        int v = (t >= off) ? ps[t - off] : 0;
        __syncthreads();
        ps[t] += v;
        __syncthreads();
    }
    int pre = (t > 0) ? ps[t - 1] : 0;
#pragma unroll
    for (int i = 0; i < 20; i++) {
        int idx = base + i;
        if (idx < NN) {
            g_off[idx] = pre + local[i];
            g_pos[idx] = pre + local[i];
        }
    }
    if (t == 1023) g_off[NN] = ps[1023];
}

__global__ void fill_kernel(const int* __restrict__ nbr,
                            const int* __restrict__ species) {
    int e = blockIdx.x * blockDim.x + threadIdx.x;
    if (e >= EE) return;
    int src = e / NEIGH;
    int dst = nbr[e];
    int et = species[src] + species[dst];
    int p = atomicAdd(&g_pos[dst], 1);
    g_rev[p] = (src << 2) | et;
}

// ---------------- gather aggregation --------------------------------------------
template<int OUT>
__global__ void gather_kernel(const float* __restrict__ bias,
                              __half* __restrict__ ox,
                              float* __restrict__ of) {
    int tid = threadIdx.x;
    int dst = blockIdx.x * 4 + (tid >> 6);
    int h = tid & 63;
    if (dst >= NN) return;
    int c0 = g_cnt[dst * 3 + 0], c1 = g_cnt[dst * 3 + 1], c2 = g_cnt[dst * 3 + 2];
    float inv0 = 1.0f / (float)(c0 > 0 ? c0 : 1);
    float inv1 = 1.0f / (float)(c1 > 0 ? c1 : 1);
    float inv2 = 1.0f / (float)(c2 > 0 ? c2 : 1);
    float v = g_H[(size_t)dst * 256 + h] + bias[h];
    int b0 = g_off[dst], b1 = g_off[dst + 1];
    for (int p = b0; p < b1; p++) {
        int pk = g_rev[p];
        int src = pk >> 2, et = pk & 3;
        float ic = (et == 0) ? inv0 : ((et == 1) ? inv1 : inv2);
        v += g_H[(size_t)src * 256 + (et + 1) * 64 + h] * ic;
    }
    v = v > 0.f ? v : 0.f;
    if (OUT == 0) ox[dst * 64 + h] = __float2half_rn(v);
    else          of[dst * 64 + h] = v;
}

// ---------------- pooling + FC ---------------------------------------------------
#define POOL_NODES 160
__global__ void pool_kernel(const int* __restrict__ crys) {
    __shared__ int starts[NCRYS];
    int t = threadIdx.x;
    if (t < NCRYS) starts[t] = crys[t * 2];
    __syncthreads();
    int v0 = blockIdx.x * POOL_NODES;
    int v1 = v0 + POOL_NODES;
    if (v1 > NN) v1 = NN;
    const float* srcbuf = (t < 64) ? g_bf : g_af;
    int h = t & 63;
    float sum = 0.f;
    int cur = -2;
    for (int v = v0; v < v1; v++) {
        int c = 0;
#pragma unroll
        for (int k = 1; k < NCRYS; k++)
            if (starts[k] <= v) c = k;
        if (c != cur) {
            if (cur >= 0) atomicAdd(&g_pool[cur * 128 + t], sum);
            sum = 0.f;
            cur = c;
        }
        sum += srcbuf[v * 64 + h];
    }
    if (cur >= 0) atomicAdd(&g_pool[cur * 128 + t], sum);
}

__global__ void fc_kernel(const int* __restrict__ crys,
                          const float* __restrict__ W,
                          const float* __restrict__ b,
                          float* __restrict__ out) {
    int t = threadIdx.x;
    if (t >= NCRYS * 2) return;
    int c = t >> 1, o = t & 1;
    float cnt = (float)(crys[c * 2 + 1] - crys[c * 2]);
    float inv = 1.0f / cnt;
    float s = 0.f;
    for (int h = 0; h < 128; h++)
        s += g_pool[c * 128 + h] * inv * W[h * 2 + o];
    out[t] = s + b[o];
}

// ---------------- launch ----------------------------------------------------------
extern "C" void kernel_launch(void* const* d_in, const int* in_sizes, int n_in,
                              void* d_out, int out_size) {
    const float* bond     = (const float*)d_in[0];
    const float* angle    = (const float*)d_in[1];
    const int*   species  = (const int*)d_in[2];
    const int*   nbr      = (const int*)d_in[3];
    const int*   crys     = (const int*)d_in[4];
    const float* W1b_rel  = (const float*)d_in[5];
    const float* W1b_root = (const float*)d_in[6];
    const float* b1b      = (const float*)d_in[7];
    const float* W1a_rel  = (const float*)d_in[8];
    const float* W1a_root = (const float*)d_in[9];
    const float* b1a      = (const float*)d_in[10];
    const float* W2b_rel  = (const float*)d_in[11];
    const float* W2b_root = (const float*)d_in[12];
    const float* b2b      = (const float*)d_in[13];
    const float* W2a_rel  = (const float*)d_in[14];
    const float* W2a_root = (const float*)d_in[15];
    const float* b2a      = (const float*)d_in[16];
    const float* fcW      = (const float*)d_in[17];
    const float* fcb      = (const float*)d_in[18];
    float* out = (float*)d_out;

    cudaFuncSetAttribute(gemm_mma, cudaFuncAttributeMaxDynamicSharedMemorySize, SMEM_GEMM);

    __half *X, *Wt, *bfx, *afx;
    float *bfp, *afp;
    cudaGetSymbolAddress((void**)&X,   g_X);
    cudaGetSymbolAddress((void**)&Wt,  g_Wt);
    cudaGetSymbolAddress((void**)&bfx, g_bfx);
    cudaGetSymbolAddress((void**)&afx, g_afx);
    cudaGetSymbolAddress((void**)&bfp, g_bf);
    cudaGetSymbolAddress((void**)&afp, g_af);

    const int T = 256;
    dim3 ggrid((NN + 127) / 128, 2);   // (157, 2) -> 2 CTAs/SM
    const int GGRID = (NN + 3) / 4;

    // slot 3 = angle GEMM (profiled)
    zero_kernel<<<(NN * 3 + T - 1) / T, T>>>();                              // 0
    expand_angle<<<(NN * 72 + T - 1) / T, T>>>(angle);                       // 1
    prep_wT<<<dim3(INA / 32, 4), 256>>>(W1a_root, W1a_rel, INA);             // 2
    gemm_mma<<<ggrid, 256, SMEM_GEMM>>>(X, Wt, INA);                         // 3 <- profiled
    count_kernel<<<(EE + T - 1) / T, T>>>(nbr, species);
    scan_kernel<<<1, 1024>>>();
    fill_kernel<<<(EE + T - 1) / T, T>>>(nbr, species);
    gather_kernel<0><<<GGRID, 256>>>(b1a, afx, nullptr);

    // --- bond, layer 1
    expand_bond<<<(NN * NEIGH + T - 1) / T, T>>>(bond);
    prep_wT<<<dim3(INB / 32, 4), 256>>>(W1b_root, W1b_rel, INB);
    gemm_mma<<<ggrid, 256, SMEM_GEMM>>>(X, Wt, INB);
    gather_kernel<0><<<GGRID, 256>>>(b1b, bfx, nullptr);

    // --- bond, layer 2
    prep_wT<<<dim3(HD / 32, 4), 256>>>(W2b_root, W2b_rel, HD);
    gemm_mma<<<ggrid, 256, SMEM_GEMM>>>(bfx, Wt, HD);
    gather_kernel<1><<<GGRID, 256>>>(b2b, nullptr, bfp);

    // --- angle, layer 2
    prep_wT<<<dim3(HD / 32, 4), 256>>>(W2a_root, W2a_rel, HD);
    gemm_mma<<<ggrid, 256, SMEM_GEMM>>>(afx, Wt, HD);
    gather_kernel<1><<<GGRID, 256>>>(b2a, nullptr, afp);

    // --- pooling + FC
    pool_kernel<<<(NN + POOL_NODES - 1) / POOL_NODES, 128>>>(crys);
    fc_kernel<<<1, 64>>>(crys, fcW, fcb, out);
}

// round 13
// speedup vs baseline: 4.2099x; 1.2022x over previous
#include <cuda_runtime.h>
#include <cuda_fp16.h>
#include <cstdint>

#define NN     20000
#define NEIGH  12
#define EE     (NN*NEIGH)
#define HD     64
#define INB    480
#define INA    2880
#define NCRYS  20

// ---------------- scratch ----------------------------------------------------
__device__ __align__(256) __half g_Xa[(size_t)NN * INA];
__device__ __align__(256) __half g_Xb[(size_t)NN * INB];
__device__ __align__(256) __half g_Wta[256 * INA];
__device__ __align__(256) __half g_Wtb[256 * INB];
__device__ __align__(256) __half g_Wt2a[256 * HD];
__device__ __align__(256) __half g_Wt2b[256 * HD];
__device__ float g_Ha[(size_t)NN * 256];
__device__ float g_Hb[(size_t)NN * 256];
__device__ float g_bf[NN * HD];
__device__ float g_af[NN * HD];
__device__ __align__(256) __half g_bfx[NN * HD];
__device__ __align__(256) __half g_afx[NN * HD];
__device__ int   g_cnt[NN * 3];
__device__ int   g_deg[NN];
__device__ int   g_off[NN + 1];
__device__ int   g_pos[NN];
__device__ int   g_rev[EE];
__device__ float g_pool[NCRYS * 128];

// ---------------- helpers ------------------------------------------------------
__device__ __forceinline__ uint32_t smem_u32(const void* p) {
    uint32_t a;
    asm("{ .reg .u64 t; cvta.to.shared.u64 t, %1; cvt.u32.u64 %0, t; }"
        : "=r"(a) : "l"(p));
    return a;
}

__device__ __forceinline__ void cp16(uint32_t dst, const void* src, int sz) {
    asm volatile("cp.async.cg.shared.global [%0], [%1], 16, %2;"
                 :: "r"(dst), "l"(src), "r"(sz));
}

__device__ __forceinline__ void ldmx4(uint32_t* r, uint32_t addr) {
    asm volatile("ldmatrix.sync.aligned.m8n8.x4.shared.b16 {%0,%1,%2,%3}, [%4];"
                 : "=r"(r[0]), "=r"(r[1]), "=r"(r[2]), "=r"(r[3]) : "r"(addr));
}

__device__ __forceinline__ void mma16816(float* c, const uint32_t* a, const uint32_t* b) {
    asm volatile(
        "mma.sync.aligned.m16n8k16.row.col.f32.f16.f16.f32 "
        "{%0,%1,%2,%3}, {%4,%5,%6,%7}, {%8,%9}, {%0,%1,%2,%3};"
        : "+f"(c[0]), "+f"(c[1]), "+f"(c[2]), "+f"(c[3])
        : "r"(a[0]), "r"(a[1]), "r"(a[2]), "r"(a[3]), "r"(b[0]), "r"(b[1]));
}

// ---------------- standalone Gaussian expansions --------------------------------
__global__ void expand_bond(const float* __restrict__ bond) {
    int idx = blockIdx.x * blockDim.x + threadIdx.x;
    if (idx >= NN * NEIGH) return;
    int v = idx / NEIGH, j = idx - v * NEIGH;
    float d = bond[idx];
    uint32_t hw[20];
#pragma unroll
    for (int i = 0; i < 20; i++) {
        uint32_t h2 = 0;
#pragma unroll
        for (int q = 0; q < 2; q++) {
            float t = d - (float)(2 * i + q) * (8.0f / 39.0f);
            float x = __expf(-t * t * 25.0f);
            h2 |= (uint32_t)__half_as_ushort(__float2half_rn(x)) << (16 * q);
        }
        hw[i] = h2;
    }
    uint4* ph = (uint4*)(g_Xb + (size_t)v * INB + j * 40);
#pragma unroll
    for (int u = 0; u < 5; u++)
        ph[u] = make_uint4(hw[4*u], hw[4*u+1], hw[4*u+2], hw[4*u+3]);
}

__global__ void expand_angle(const float* __restrict__ ang) {
    int idx = blockIdx.x * blockDim.x + threadIdx.x;
    if (idx >= NN * 72) return;
    int v = idx / 72, p = idx - v * 72;
    float d0 = ang[(size_t)v * 144 + 2 * p];
    float d1 = ang[(size_t)v * 144 + 2 * p + 1];
    uint32_t hw[20];
#pragma unroll
    for (int half = 0; half < 2; half++) {
        float d = half ? d1 : d0;
#pragma unroll
        for (int i = 0; i < 10; i++) {
            uint32_t h2 = 0;
#pragma unroll
            for (int q = 0; q < 2; q++) {
                float t = d - (-1.0f + (float)(2 * i + q) * (2.0f / 19.0f));
                float x = __expf(-t * t * 100.0f);
                h2 |= (uint32_t)__half_as_ushort(__float2half_rn(x)) << (16 * q);
            }
            hw[half * 10 + i] = h2;
        }
    }
    uint4* ph = (uint4*)(g_Xa + (size_t)v * INA + p * 40);
#pragma unroll
    for (int u = 0; u < 5; u++)
        ph[u] = make_uint4(hw[4*u], hw[4*u+1], hw[4*u+2], hw[4*u+3]);
}

// ---------------- GEMM: H[M,256] = X @ W^T (single fp16 pass) -------------------
#define SM_A  0
#define SM_B  10240
#define STAGE 20480
#define SMEM_GEMM (4 * STAGE)

__device__ __forceinline__ void load_chunk(uint32_t sb, int c,
                                           const __half* A, const __half* B,
                                           int K, int m0, int n0, int tid) {
#pragma unroll
    for (int q = 0; q < 2; q++) {
        int j = tid + q * 256;
        int row = j >> 2, cc = j & 3;
        uint32_t doff = (uint32_t)(row * 80 + cc * 16);
        int gm = m0 + row;
        int gmc = gm < NN ? gm : 0;
        int sz = gm < NN ? 16 : 0;
        cp16(sb + SM_A + doff, A + (size_t)gmc * K + c * 32 + cc * 8, sz);
        cp16(sb + SM_B + doff, B + (size_t)(n0 + row) * K + c * 32 + cc * 8, 16);
    }
    asm volatile("cp.async.commit_group;" ::: "memory");
}

__global__ __launch_bounds__(256, 2)
void gemm_mma(const __half* __restrict__ A,
              const __half* __restrict__ B,
              float* __restrict__ H,
              int K) {
    extern __shared__ char smem[];
    uint32_t sbase = smem_u32(smem);
    int tid = threadIdx.x;
    int w = tid >> 5, l = tid & 31;
    int m0 = blockIdx.x * 128;
    int n0 = blockIdx.y * 128;
    int warp_m = (w >> 1) * 32;
    int warp_n = (w & 1) * 64;
    int nchunks = K >> 5;

    float acc[2][8][4];
#pragma unroll
    for (int i = 0; i < 2; i++)
#pragma unroll
        for (int j = 0; j < 8; j++)
#pragma unroll
            for (int q = 0; q < 4; q++) acc[i][j][q] = 0.f;

    uint32_t a_off[2];
#pragma unroll
    for (int mt = 0; mt < 2; mt++)
        a_off[mt] = (uint32_t)((warp_m + mt * 16 + (l & 15)) * 80 + ((l >> 4) * 16));
    uint32_t b_base = (uint32_t)((warp_n + (l & 7) + ((l >> 4) << 3)) * 80 +
                                 (((l >> 3) & 1) * 16));

    load_chunk(sbase, 0, A, B, K, m0, n0, tid);
    if (nchunks > 1) load_chunk(sbase + STAGE, 1, A, B, K, m0, n0, tid);
    if (nchunks > 2) load_chunk(sbase + 2 * STAGE, 2, A, B, K, m0, n0, tid);

    int st = 0;
    for (int c = 0; c < nchunks; c++) {
        int rem = nchunks - 1 - c;
        if (rem >= 2)      asm volatile("cp.async.wait_group 2;" ::: "memory");
        else if (rem == 1) asm volatile("cp.async.wait_group 1;" ::: "memory");
        else               asm volatile("cp.async.wait_group 0;" ::: "memory");
        __syncthreads();

        uint32_t sb = sbase + (uint32_t)(st * STAGE);
#pragma unroll
        for (int s = 0; s < 2; s++) {
            uint32_t af[2][4];
#pragma unroll
            for (int mt = 0; mt < 2; mt++)
                ldmx4(af[mt], sb + SM_A + a_off[mt] + s * 32);
#pragma unroll
            for (int p = 0; p < 4; p++) {
                uint32_t rb[4];
                ldmx4(rb, sb + SM_B + b_base + (uint32_t)(p * 1280) + s * 32);
#pragma unroll
                for (int mt = 0; mt < 2; mt++) {
                    mma16816(acc[mt][2 * p],     af[mt], rb);
                    mma16816(acc[mt][2 * p + 1], af[mt], rb + 2);
                }
            }
        }
        if (c + 3 < nchunks) {
            int st3 = (st + 3) & 3;
            load_chunk(sbase + (uint32_t)(st3 * STAGE), c + 3, A, B, K, m0, n0, tid);
        }
        st = (st + 1) & 3;
    }

#pragma unroll
    for (int mt = 0; mt < 2; mt++) {
        int m1 = m0 + warp_m + mt * 16 + (l >> 2);
        int m2 = m1 + 8;
#pragma unroll
        for (int nt = 0; nt < 8; nt++) {
            int nc = n0 + warp_n + nt * 8 + 2 * (l & 3);
            if (m1 < NN)
                *(float2*)(H + (size_t)m1 * 256 + nc) =
                    make_float2(acc[mt][nt][0], acc[mt][nt][1]);
            if (m2 < NN)
                *(float2*)(H + (size_t)m2 * 256 + nc) =
                    make_float2(acc[mt][nt][2], acc[mt][nt][3]);
        }
    }
}

// ---------------- weight transpose + fp16 convert ------------------------------
__global__ void prep_wT(const float* __restrict__ Wroot,
                        const float* __restrict__ Wrel,
                        __half* __restrict__ Wt, int K) {
    __shared__ float sm[32][65];
    int tid = threadIdx.x;
    int k0 = blockIdx.x * 32;
    int cb = blockIdx.y;
#pragma unroll
    for (int i = 0; i < 8; i++) {
        int e = tid + i * 256;
        int k = e >> 6, h = e & 63;
        float wv = (cb == 0) ? Wroot[(size_t)(k0 + k) * 64 + h]
                             : Wrel[(size_t)(cb - 1) * K * 64 + (size_t)(k0 + k) * 64 + h];
        sm[k][h] = wv;
    }
    __syncthreads();
#pragma unroll
    for (int i = 0; i < 8; i++) {
        int e = tid + i * 256;
        int h = e >> 5, kk = e & 31;
        Wt[(size_t)(cb * 64 + h) * K + k0 + kk] = __float2half_rn(sm[kk][h]);
    }
}

// ---------------- graph preprocessing ------------------------------------------
__global__ void zero_kernel() {
    int i = blockIdx.x * blockDim.x + threadIdx.x;
    if (i < NN * 3) g_cnt[i] = 0;
    if (i < NN) g_deg[i] = 0;
    if (i < NCRYS * 128) g_pool[i] = 0.f;
}

__global__ void count_kernel(const int* __restrict__ nbr,
                             const int* __restrict__ species) {
    int e = blockIdx.x * blockDim.x + threadIdx.x;
    if (e >= EE) return;
    int src = e / NEIGH;
    int dst = nbr[e];
    int et = species[src] + species[dst];
    atomicAdd(&g_cnt[dst * 3 + et], 1);
    atomicAdd(&g_deg[dst], 1);
}

__global__ void scan_kernel() {
    __shared__ int ps[1024];
    int t = threadIdx.x;
    int base = t * 20;
    int local[20];
    int s = 0;
#pragma unroll
    for (int i = 0; i < 20; i++) {
        int idx = base + i;
        int d = (idx < NN) ? g_deg[idx] : 0;
        local[i] = s;
        s += d;
    }
    ps[t] = s;
    __syncthreads();
    for (int off = 1; off < 1024; off <<= 1) {
        int v = (t >= off) ? ps[t - off] : 0;
        __syncthreads();
        ps[t] += v;
        __syncthreads();
    }
    int pre = (t > 0) ? ps[t - 1] : 0;
#pragma unroll
    for (int i = 0; i < 20; i++) {
        int idx = base + i;
        if (idx < NN) {
            g_off[idx] = pre + local[i];
            g_pos[idx] = pre + local[i];
        }
    }
    if (t == 1023) g_off[NN] = ps[1023];
}

__global__ void fill_kernel(const int* __restrict__ nbr,
                            const int* __restrict__ species) {
    int e = blockIdx.x * blockDim.x + threadIdx.x;
    if (e >= EE) return;
    int src = e / NEIGH;
    int dst = nbr[e];
    int et = species[src] + species[dst];
    int p = atomicAdd(&g_pos[dst], 1);
    g_rev[p] = (src << 2) | et;
}

// ---------------- gather aggregation --------------------------------------------
template<int OUT>
__global__ void gather_kernel(const float* __restrict__ H,
                              const float* __restrict__ bias,
                              __half* __restrict__ ox,
                              float* __restrict__ of) {
    int tid = threadIdx.x;
    int dst = blockIdx.x * 4 + (tid >> 6);
    int h = tid & 63;
    if (dst >= NN) return;
    int c0 = g_cnt[dst * 3 + 0], c1 = g_cnt[dst * 3 + 1], c2 = g_cnt[dst * 3 + 2];
    float inv0 = 1.0f / (float)(c0 > 0 ? c0 : 1);
    float inv1 = 1.0f / (float)(c1 > 0 ? c1 : 1);
    float inv2 = 1.0f / (float)(c2 > 0 ? c2 : 1);
    float v = H[(size_t)dst * 256 + h] + bias[h];
    int b0 = g_off[dst], b1 = g_off[dst + 1];
    for (int p = b0; p < b1; p++) {
        int pk = g_rev[p];
        int src = pk >> 2, et = pk & 3;
        float ic = (et == 0) ? inv0 : ((et == 1) ? inv1 : inv2);
        v += H[(size_t)src * 256 + (et + 1) * 64 + h] * ic;
    }
    v = v > 0.f ? v : 0.f;
    if (OUT == 0) ox[dst * 64 + h] = __float2half_rn(v);
    else          of[dst * 64 + h] = v;
}

// ---------------- pooling + FC ---------------------------------------------------
#define POOL_NODES 160
__global__ void pool_kernel(const int* __restrict__ crys) {
    __shared__ int starts[NCRYS];
    int t = threadIdx.x;
    if (t < NCRYS) starts[t] = crys[t * 2];
    __syncthreads();
    int v0 = blockIdx.x * POOL_NODES;
    int v1 = v0 + POOL_NODES;
    if (v1 > NN) v1 = NN;
    const float* srcbuf = (t < 64) ? g_bf : g_af;
    int h = t & 63;
    float sum = 0.f;
    int cur = -2;
    for (int v = v0; v < v1; v++) {
        int c = 0;
#pragma unroll
        for (int k = 1; k < NCRYS; k++)
            if (starts[k] <= v) c = k;
        if (c != cur) {
            if (cur >= 0) atomicAdd(&g_pool[cur * 128 + t], sum);
            sum = 0.f;
            cur = c;
        }
        sum += srcbuf[v * 64 + h];
    }
    if (cur >= 0) atomicAdd(&g_pool[cur * 128 + t], sum);
}

__global__ void fc_kernel(const int* __restrict__ crys,
                          const float* __restrict__ W,
                          const float* __restrict__ b,
                          float* __restrict__ out) {
    int t = threadIdx.x;
    if (t >= NCRYS * 2) return;
    int c = t >> 1, o = t & 1;
    float cnt = (float)(crys[c * 2 + 1] - crys[c * 2]);
    float inv = 1.0f / cnt;
    float s = 0.f;
    for (int h = 0; h < 128; h++)
        s += g_pool[c * 128 + h] * inv * W[h * 2 + o];
    out[t] = s + b[o];
}

// ---------------- launch ----------------------------------------------------------
extern "C" void kernel_launch(void* const* d_in, const int* in_sizes, int n_in,
                              void* d_out, int out_size) {
    const float* bond     = (const float*)d_in[0];
    const float* angle    = (const float*)d_in[1];
    const int*   species  = (const int*)d_in[2];
    const int*   nbr      = (const int*)d_in[3];
    const int*   crys     = (const int*)d_in[4];
    const float* W1b_rel  = (const float*)d_in[5];
    const float* W1b_root = (const float*)d_in[6];
    const float* b1b      = (const float*)d_in[7];
    const float* W1a_rel  = (const float*)d_in[8];
    const float* W1a_root = (const float*)d_in[9];
    const float* b1a      = (const float*)d_in[10];
    const float* W2b_rel  = (const float*)d_in[11];
    const float* W2b_root = (const float*)d_in[12];
    const float* b2b      = (const float*)d_in[13];
    const float* W2a_rel  = (const float*)d_in[14];
    const float* W2a_root = (const float*)d_in[15];
    const float* b2a      = (const float*)d_in[16];
    const float* fcW      = (const float*)d_in[17];
    const float* fcb      = (const float*)d_in[18];
    float* out = (float*)d_out;

    static cudaStream_t sB = nullptr;
    static cudaEvent_t evFork, evGraph, evJoin;
    if (!sB) {
        cudaStreamCreateWithFlags(&sB, cudaStreamNonBlocking);
        cudaEventCreateWithFlags(&evFork,  cudaEventDisableTiming);
        cudaEventCreateWithFlags(&evGraph, cudaEventDisableTiming);
        cudaEventCreateWithFlags(&evJoin,  cudaEventDisableTiming);
    }

    cudaFuncSetAttribute(gemm_mma, cudaFuncAttributeMaxDynamicSharedMemorySize, SMEM_GEMM);

    __half *Xa, *Xb, *Wta, *Wtb, *Wt2a, *Wt2b, *bfx, *afx;
    float *Ha, *Hb, *bfp, *afp;
    cudaGetSymbolAddress((void**)&Xa,  g_Xa);
    cudaGetSymbolAddress((void**)&Xb,  g_Xb);
    cudaGetSymbolAddress((void**)&Wta, g_Wta);
    cudaGetSymbolAddress((void**)&Wtb, g_Wtb);
    cudaGetSymbolAddress((void**)&Wt2a, g_Wt2a);
    cudaGetSymbolAddress((void**)&Wt2b, g_Wt2b);
    cudaGetSymbolAddress((void**)&Ha,  g_Ha);
    cudaGetSymbolAddress((void**)&Hb,  g_Hb);
    cudaGetSymbolAddress((void**)&bfx, g_bfx);
    cudaGetSymbolAddress((void**)&afx, g_afx);
    cudaGetSymbolAddress((void**)&bfp, g_bf);
    cudaGetSymbolAddress((void**)&afp, g_af);

    const int T = 256;
    dim3 ggrid((NN + 127) / 128, 2);
    const int GGRID = (NN + 3) / 4;

    // ---- default stream: zero, then fork bond chain ----
    zero_kernel<<<(NN * 3 + T - 1) / T, T>>>();
    cudaEventRecord(evFork, 0);
    cudaStreamWaitEvent(sB, evFork, 0);

    // ---- default stream: graph preprocessing (off critical path) ----
    count_kernel<<<(EE + T - 1) / T, T>>>(nbr, species);
    scan_kernel<<<1, 1024>>>();
    fill_kernel<<<(EE + T - 1) / T, T>>>(nbr, species);
    cudaEventRecord(evGraph, 0);

    // ---- bond chain on stream sB ----
    expand_bond<<<(NN * NEIGH + T - 1) / T, T, 0, sB>>>(bond);
    prep_wT<<<dim3(INB / 32, 4), 256, 0, sB>>>(W1b_root, W1b_rel, Wtb, INB);
    gemm_mma<<<ggrid, 256, SMEM_GEMM, sB>>>(Xb, Wtb, Hb, INB);
    cudaStreamWaitEvent(sB, evGraph, 0);
    gather_kernel<0><<<GGRID, 256, 0, sB>>>(Hb, b1b, bfx, nullptr);
    prep_wT<<<dim3(HD / 32, 4), 256, 0, sB>>>(W2b_root, W2b_rel, Wt2b, HD);
    gemm_mma<<<ggrid, 256, SMEM_GEMM, sB>>>(bfx, Wt2b, Hb, HD);
    gather_kernel<1><<<GGRID, 256, 0, sB>>>(Hb, b2b, nullptr, bfp);
    cudaEventRecord(evJoin, sB);

    // ---- angle chain on default stream (critical path) ----
    expand_angle<<<(NN * 72 + T - 1) / T, T>>>(angle);
    prep_wT<<<dim3(INA / 32, 4), 256>>>(W1a_root, W1a_rel, Wta, INA);
    gemm_mma<<<ggrid, 256, SMEM_GEMM>>>(Xa, Wta, Ha, INA);
    gather_kernel<0><<<GGRID, 256>>>(Ha, b1a, afx, nullptr);
    prep_wT<<<dim3(HD / 32, 4), 256>>>(W2a_root, W2a_rel, Wt2a, HD);
    gemm_mma<<<ggrid, 256, SMEM_GEMM>>>(afx, Wt2a, Ha, HD);
    gather_kernel<1><<<GGRID, 256>>>(Ha, b2a, nullptr, afp);

    // ---- join + pooling + FC ----
    cudaStreamWaitEvent(0, evJoin, 0);
    pool_kernel<<<(NN + POOL_NODES - 1) / POOL_NODES, 128>>>(crys);
    fc_kernel<<<1, 64>>>(crys, fcW, fcb, out);
}

// round 14
// speedup vs baseline: 4.3468x; 1.0325x over previous
#include <cuda_runtime.h>
#include <cuda_fp16.h>
#include <cstdint>

#define NN     20000
#define NEIGH  12
#define EE     (NN*NEIGH)
#define HD     64
#define INB    480
#define INA    2880
#define NCRYS  20

// ---------------- scratch ----------------------------------------------------
__device__ __align__(256) __half g_Xa[(size_t)NN * INA];
__device__ __align__(256) __half g_Xb[(size_t)NN * INB];
__device__ __align__(256) __half g_Wta[256 * INA];
__device__ __align__(256) __half g_Wtb[256 * INB];
__device__ __align__(256) __half g_Wt2a[256 * HD];
__device__ __align__(256) __half g_Wt2b[256 * HD];
__device__ float g_Ha[(size_t)NN * 256];
__device__ float g_Hb[(size_t)NN * 256];
__device__ float g_bf[NN * HD];
__device__ float g_af[NN * HD];
__device__ __align__(256) __half g_bfx[NN * HD];
__device__ __align__(256) __half g_afx[NN * HD];
__device__ int   g_cnt[NN * 3];
__device__ int   g_deg[NN];
__device__ int   g_off[NN + 1];
__device__ int   g_pos[NN];
__device__ int   g_rev[EE];
__device__ float g_pool[NCRYS * 128];

// ---------------- helpers ------------------------------------------------------
__device__ __forceinline__ uint32_t smem_u32(const void* p) {
    uint32_t a;
    asm("{ .reg .u64 t; cvta.to.shared.u64 t, %1; cvt.u32.u64 %0, t; }"
        : "=r"(a) : "l"(p));
    return a;
}

__device__ __forceinline__ void cp16(uint32_t dst, const void* src, int sz) {
    asm volatile("cp.async.cg.shared.global [%0], [%1], 16, %2;"
                 :: "r"(dst), "l"(src), "r"(sz));
}

__device__ __forceinline__ void ldmx4(uint32_t* r, uint32_t addr) {
    asm volatile("ldmatrix.sync.aligned.m8n8.x4.shared.b16 {%0,%1,%2,%3}, [%4];"
                 : "=r"(r[0]), "=r"(r[1]), "=r"(r[2]), "=r"(r[3]) : "r"(addr));
}

__device__ __forceinline__ void mma16816(float* c, const uint32_t* a, const uint32_t* b) {
    asm volatile(
        "mma.sync.aligned.m16n8k16.row.col.f32.f16.f16.f32 "
        "{%0,%1,%2,%3}, {%4,%5,%6,%7}, {%8,%9}, {%0,%1,%2,%3};"
        : "+f"(c[0]), "+f"(c[1]), "+f"(c[2]), "+f"(c[3])
        : "r"(a[0]), "r"(a[1]), "r"(a[2]), "r"(a[3]), "r"(b[0]), "r"(b[1]));
}

// ---------------- standalone Gaussian expansions --------------------------------
__global__ void expand_bond(const float* __restrict__ bond) {
    int idx = blockIdx.x * blockDim.x + threadIdx.x;
    if (idx >= NN * NEIGH) return;
    int v = idx / NEIGH, j = idx - v * NEIGH;
    float d = bond[idx];
    uint32_t hw[20];
#pragma unroll
    for (int i = 0; i < 20; i++) {
        uint32_t h2 = 0;
#pragma unroll
        for (int q = 0; q < 2; q++) {
            float t = d - (float)(2 * i + q) * (8.0f / 39.0f);
            float x = __expf(-t * t * 25.0f);
            h2 |= (uint32_t)__half_as_ushort(__float2half_rn(x)) << (16 * q);
        }
        hw[i] = h2;
    }
    uint4* ph = (uint4*)(g_Xb + (size_t)v * INB + j * 40);
#pragma unroll
    for (int u = 0; u < 5; u++)
        ph[u] = make_uint4(hw[4*u], hw[4*u+1], hw[4*u+2], hw[4*u+3]);
}

__global__ void expand_angle(const float* __restrict__ ang) {
    int idx = blockIdx.x * blockDim.x + threadIdx.x;
    if (idx >= NN * 72) return;
    int v = idx / 72, p = idx - v * 72;
    float d0 = ang[(size_t)v * 144 + 2 * p];
    float d1 = ang[(size_t)v * 144 + 2 * p + 1];
    uint32_t hw[20];
#pragma unroll
    for (int half = 0; half < 2; half++) {
        float d = half ? d1 : d0;
#pragma unroll
        for (int i = 0; i < 10; i++) {
            uint32_t h2 = 0;
#pragma unroll
            for (int q = 0; q < 2; q++) {
                float t = d - (-1.0f + (float)(2 * i + q) * (2.0f / 19.0f));
                float x = __expf(-t * t * 100.0f);
                h2 |= (uint32_t)__half_as_ushort(__float2half_rn(x)) << (16 * q);
            }
            hw[half * 10 + i] = h2;
        }
    }
    uint4* ph = (uint4*)(g_Xa + (size_t)v * INA + p * 40);
#pragma unroll
    for (int u = 0; u < 5; u++)
        ph[u] = make_uint4(hw[4*u], hw[4*u+1], hw[4*u+2], hw[4*u+3]);
}

// ---------------- GEMM: H[M,256] = X @ W^T (single fp16 pass) -------------------
#define SM_A  0
#define SM_B  10240
#define STAGE 20480
#define SMEM_GEMM (4 * STAGE)

__device__ __forceinline__ void load_chunk(uint32_t sb, int c,
                                           const __half* A, const __half* B,
                                           int K, int m0, int n0, int tid) {
#pragma unroll
    for (int q = 0; q < 2; q++) {
        int j = tid + q * 256;
        int row = j >> 2, cc = j & 3;
        uint32_t doff = (uint32_t)(row * 80 + cc * 16);
        int gm = m0 + row;
        int gmc = gm < NN ? gm : 0;
        int sz = gm < NN ? 16 : 0;
        cp16(sb + SM_A + doff, A + (size_t)gmc * K + c * 32 + cc * 8, sz);
        cp16(sb + SM_B + doff, B + (size_t)(n0 + row) * K + c * 32 + cc * 8, 16);
    }
    asm volatile("cp.async.commit_group;" ::: "memory");
}

__global__ __launch_bounds__(256, 2)
void gemm_mma(const __half* __restrict__ A,
              const __half* __restrict__ B,
              float* __restrict__ H,
              int K) {
    extern __shared__ char smem[];
    uint32_t sbase = smem_u32(smem);
    int tid = threadIdx.x;
    int w = tid >> 5, l = tid & 31;
    int m0 = blockIdx.x * 128;
    int n0 = blockIdx.y * 128;
    int warp_m = (w >> 1) * 32;
    int warp_n = (w & 1) * 64;
    int nchunks = K >> 5;

    float acc[2][8][4];
#pragma unroll
    for (int i = 0; i < 2; i++)
#pragma unroll
        for (int j = 0; j < 8; j++)
#pragma unroll
            for (int q = 0; q < 4; q++) acc[i][j][q] = 0.f;

    uint32_t a_off[2];
#pragma unroll
    for (int mt = 0; mt < 2; mt++)
        a_off[mt] = (uint32_t)((warp_m + mt * 16 + (l & 15)) * 80 + ((l >> 4) * 16));
    uint32_t b_base = (uint32_t)((warp_n + (l & 7) + ((l >> 4) << 3)) * 80 +
                                 (((l >> 3) & 1) * 16));

    load_chunk(sbase, 0, A, B, K, m0, n0, tid);
    if (nchunks > 1) load_chunk(sbase + STAGE, 1, A, B, K, m0, n0, tid);
    if (nchunks > 2) load_chunk(sbase + 2 * STAGE, 2, A, B, K, m0, n0, tid);

    int st = 0;
    for (int c = 0; c < nchunks; c++) {
        int rem = nchunks - 1 - c;
        if (rem >= 2)      asm volatile("cp.async.wait_group 2;" ::: "memory");
        else if (rem == 1) asm volatile("cp.async.wait_group 1;" ::: "memory");
        else               asm volatile("cp.async.wait_group 0;" ::: "memory");
        __syncthreads();

        uint32_t sb = sbase + (uint32_t)(st * STAGE);
#pragma unroll
        for (int s = 0; s < 2; s++) {
            uint32_t af[2][4];
#pragma unroll
            for (int mt = 0; mt < 2; mt++)
                ldmx4(af[mt], sb + SM_A + a_off[mt] + s * 32);
#pragma unroll
            for (int p = 0; p < 4; p++) {
                uint32_t rb[4];
                ldmx4(rb, sb + SM_B + b_base + (uint32_t)(p * 1280) + s * 32);
#pragma unroll
                for (int mt = 0; mt < 2; mt++) {
                    mma16816(acc[mt][2 * p],     af[mt], rb);
                    mma16816(acc[mt][2 * p + 1], af[mt], rb + 2);
                }
            }
        }
        if (c + 3 < nchunks) {
            int st3 = (st + 3) & 3;
            load_chunk(sbase + (uint32_t)(st3 * STAGE), c + 3, A, B, K, m0, n0, tid);
        }
        st = (st + 1) & 3;
    }

#pragma unroll
    for (int mt = 0; mt < 2; mt++) {
        int m1 = m0 + warp_m + mt * 16 + (l >> 2);
        int m2 = m1 + 8;
#pragma unroll
        for (int nt = 0; nt < 8; nt++) {
            int nc = n0 + warp_n + nt * 8 + 2 * (l & 3);
            if (m1 < NN)
                *(float2*)(H + (size_t)m1 * 256 + nc) =
                    make_float2(acc[mt][nt][0], acc[mt][nt][1]);
            if (m2 < NN)
                *(float2*)(H + (size_t)m2 * 256 + nc) =
                    make_float2(acc[mt][nt][2], acc[mt][nt][3]);
        }
    }
}

// ---------------- weight transpose + fp16 convert ------------------------------
__global__ void prep_wT(const float* __restrict__ Wroot,
                        const float* __restrict__ Wrel,
                        __half* __restrict__ Wt, int K) {
    __shared__ float sm[32][65];
    int tid = threadIdx.x;
    int k0 = blockIdx.x * 32;
    int cb = blockIdx.y;
#pragma unroll
    for (int i = 0; i < 8; i++) {
        int e = tid + i * 256;
        int k = e >> 6, h = e & 63;
        float wv = (cb == 0) ? Wroot[(size_t)(k0 + k) * 64 + h]
                             : Wrel[(size_t)(cb - 1) * K * 64 + (size_t)(k0 + k) * 64 + h];
        sm[k][h] = wv;
    }
    __syncthreads();
#pragma unroll
    for (int i = 0; i < 8; i++) {
        int e = tid + i * 256;
        int h = e >> 5, kk = e & 31;
        Wt[(size_t)(cb * 64 + h) * K + k0 + kk] = __float2half_rn(sm[kk][h]);
    }
}

// ---------------- graph preprocessing ------------------------------------------
__global__ void zero_kernel() {
    int i = blockIdx.x * blockDim.x + threadIdx.x;
    if (i < NN * 3) g_cnt[i] = 0;
    if (i < NN) g_deg[i] = 0;
    if (i < NCRYS * 128) g_pool[i] = 0.f;
}

__global__ void count_kernel(const int* __restrict__ nbr,
                             const int* __restrict__ species) {
    int e = blockIdx.x * blockDim.x + threadIdx.x;
    if (e >= EE) return;
    int src = e / NEIGH;
    int dst = nbr[e];
    int et = species[src] + species[dst];
    atomicAdd(&g_cnt[dst * 3 + et], 1);
    atomicAdd(&g_deg[dst], 1);
}

__global__ void scan_kernel() {
    __shared__ int ps[1024];
    int t = threadIdx.x;
    int base = t * 20;
    int local[20];
    int s = 0;
#pragma unroll
    for (int i = 0; i < 20; i++) {
        int idx = base + i;
        int d = (idx < NN) ? g_deg[idx] : 0;
        local[i] = s;
        s += d;
    }
    ps[t] = s;
    __syncthreads();
    for (int off = 1; off < 1024; off <<= 1) {
        int v = (t >= off) ? ps[t - off] : 0;
        __syncthreads();
        ps[t] += v;
        __syncthreads();
    }
    int pre = (t > 0) ? ps[t - 1] : 0;
#pragma unroll
    for (int i = 0; i < 20; i++) {
        int idx = base + i;
        if (idx < NN) {
            g_off[idx] = pre + local[i];
            g_pos[idx] = pre + local[i];
        }
    }
    if (t == 1023) g_off[NN] = ps[1023];
}

__global__ void fill_kernel(const int* __restrict__ nbr,
                            const int* __restrict__ species) {
    int e = blockIdx.x * blockDim.x + threadIdx.x;
    if (e >= EE) return;
    int src = e / NEIGH;
    int dst = nbr[e];
    int et = species[src] + species[dst];
    int p = atomicAdd(&g_pos[dst], 1);
    g_rev[p] = (src << 2) | et;
}

// ---------------- gather aggregation (2-way split edge loop) --------------------
// 256 threads: 2 dst x 2 edge-slots x 64 h. Halves the serial chain per dst.
template<int OUT>
__global__ void gather_kernel(const float* __restrict__ H,
                              const float* __restrict__ bias,
                              __half* __restrict__ ox,
                              float* __restrict__ of) {
    __shared__ float part[128];
    int tid = threadIdx.x;
    int ld = tid >> 7;            // local dst 0..1
    int es = (tid >> 6) & 1;      // edge slot 0..1
    int h = tid & 63;
    int dst = blockIdx.x * 2 + ld;
    float v = 0.f;
    if (dst < NN) {
        int c0 = g_cnt[dst * 3 + 0], c1 = g_cnt[dst * 3 + 1], c2 = g_cnt[dst * 3 + 2];
        float inv0 = 1.0f / (float)(c0 > 0 ? c0 : 1);
        float inv1 = 1.0f / (float)(c1 > 0 ? c1 : 1);
        float inv2 = 1.0f / (float)(c2 > 0 ? c2 : 1);
        int b0 = g_off[dst], b1 = g_off[dst + 1];
        for (int p = b0 + es; p < b1; p += 2) {
            int pk = g_rev[p];
            int src = pk >> 2, et = pk & 3;
            float ic = (et == 0) ? inv0 : ((et == 1) ? inv1 : inv2);
            v += H[(size_t)src * 256 + (et + 1) * 64 + h] * ic;
        }
    }
    if (es == 1) part[ld * 64 + h] = v;
    __syncthreads();
    if (es == 0 && dst < NN) {
        v += part[ld * 64 + h];
        v += H[(size_t)dst * 256 + h] + bias[h];
        v = v > 0.f ? v : 0.f;
        if (OUT == 0) ox[dst * 64 + h] = __float2half_rn(v);
        else          of[dst * 64 + h] = v;
    }
}

// ---------------- pooling + FC ---------------------------------------------------
#define POOL_NODES 160
__global__ void pool_kernel(const int* __restrict__ crys) {
    __shared__ int starts[NCRYS];
    int t = threadIdx.x;
    if (t < NCRYS) starts[t] = crys[t * 2];
    __syncthreads();
    int v0 = blockIdx.x * POOL_NODES;
    int v1 = v0 + POOL_NODES;
    if (v1 > NN) v1 = NN;
    const float* srcbuf = (t < 64) ? g_bf : g_af;
    int h = t & 63;
    float sum = 0.f;
    int cur = -2;
    for (int v = v0; v < v1; v++) {
        int c = 0;
#pragma unroll
        for (int k = 1; k < NCRYS; k++)
            if (starts[k] <= v) c = k;
        if (c != cur) {
            if (cur >= 0) atomicAdd(&g_pool[cur * 128 + t], sum);
            sum = 0.f;
            cur = c;
        }
        sum += srcbuf[v * 64 + h];
    }
    if (cur >= 0) atomicAdd(&g_pool[cur * 128 + t], sum);
}

__global__ void fc_kernel(const int* __restrict__ crys,
                          const float* __restrict__ W,
                          const float* __restrict__ b,
                          float* __restrict__ out) {
    int t = threadIdx.x;
    if (t >= NCRYS * 2) return;
    int c = t >> 1, o = t & 1;
    float cnt = (float)(crys[c * 2 + 1] - crys[c * 2]);
    float inv = 1.0f / cnt;
    float s = 0.f;
    for (int h = 0; h < 128; h++)
        s += g_pool[c * 128 + h] * inv * W[h * 2 + o];
    out[t] = s + b[o];
}

// ---------------- launch ----------------------------------------------------------
extern "C" void kernel_launch(void* const* d_in, const int* in_sizes, int n_in,
                              void* d_out, int out_size) {
    const float* bond     = (const float*)d_in[0];
    const float* angle    = (const float*)d_in[1];
    const int*   species  = (const int*)d_in[2];
    const int*   nbr      = (const int*)d_in[3];
    const int*   crys     = (const int*)d_in[4];
    const float* W1b_rel  = (const float*)d_in[5];
    const float* W1b_root = (const float*)d_in[6];
    const float* b1b      = (const float*)d_in[7];
    const float* W1a_rel  = (const float*)d_in[8];
    const float* W1a_root = (const float*)d_in[9];
    const float* b1a      = (const float*)d_in[10];
    const float* W2b_rel  = (const float*)d_in[11];
    const float* W2b_root = (const float*)d_in[12];
    const float* b2b      = (const float*)d_in[13];
    const float* W2a_rel  = (const float*)d_in[14];
    const float* W2a_root = (const float*)d_in[15];
    const float* b2a      = (const float*)d_in[16];
    const float* fcW      = (const float*)d_in[17];
    const float* fcb      = (const float*)d_in[18];
    float* out = (float*)d_out;

    static cudaStream_t sB = nullptr, sC = nullptr, sD = nullptr;
    static cudaEvent_t evFork, evGraph, evPrepA, evPrep2A, evJoin;
    if (!sB) {
        cudaStreamCreateWithFlags(&sB, cudaStreamNonBlocking);
        cudaStreamCreateWithFlags(&sC, cudaStreamNonBlocking);
        cudaStreamCreateWithFlags(&sD, cudaStreamNonBlocking);
        cudaEventCreateWithFlags(&evFork,   cudaEventDisableTiming);
        cudaEventCreateWithFlags(&evGraph,  cudaEventDisableTiming);
        cudaEventCreateWithFlags(&evPrepA,  cudaEventDisableTiming);
        cudaEventCreateWithFlags(&evPrep2A, cudaEventDisableTiming);
        cudaEventCreateWithFlags(&evJoin,   cudaEventDisableTiming);
    }

    cudaFuncSetAttribute(gemm_mma, cudaFuncAttributeMaxDynamicSharedMemorySize, SMEM_GEMM);

    __half *Xa, *Xb, *Wta, *Wtb, *Wt2a, *Wt2b, *bfx, *afx;
    float *Ha, *Hb, *bfp, *afp;
    cudaGetSymbolAddress((void**)&Xa,  g_Xa);
    cudaGetSymbolAddress((void**)&Xb,  g_Xb);
    cudaGetSymbolAddress((void**)&Wta, g_Wta);
    cudaGetSymbolAddress((void**)&Wtb, g_Wtb);
    cudaGetSymbolAddress((void**)&Wt2a, g_Wt2a);
    cudaGetSymbolAddress((void**)&Wt2b, g_Wt2b);
    cudaGetSymbolAddress((void**)&Ha,  g_Ha);
    cudaGetSymbolAddress((void**)&Hb,  g_Hb);
    cudaGetSymbolAddress((void**)&bfx, g_bfx);
    cudaGetSymbolAddress((void**)&afx, g_afx);
    cudaGetSymbolAddress((void**)&bfp, g_bf);
    cudaGetSymbolAddress((void**)&afp, g_af);

    const int T = 256;
    dim3 ggrid((NN + 127) / 128, 2);
    const int GGRID = (NN + 1) / 2;      // gather: 2 dst per block

    // ---- default: zero, then fork everything ----
    zero_kernel<<<(NN * 3 + T - 1) / T, T>>>();
    cudaEventRecord(evFork, 0);
    cudaStreamWaitEvent(sB, evFork, 0);
    cudaStreamWaitEvent(sC, evFork, 0);
    cudaStreamWaitEvent(sD, evFork, 0);

    // ---- sC: graph preprocessing (fully off critical path) ----
    count_kernel<<<(EE + T - 1) / T, T, 0, sC>>>(nbr, species);
    scan_kernel<<<1, 1024, 0, sC>>>();
    fill_kernel<<<(EE + T - 1) / T, T, 0, sC>>>(nbr, species);
    cudaEventRecord(evGraph, sC);

    // ---- sD: angle weight preps (under expand_angle) ----
    prep_wT<<<dim3(INA / 32, 4), 256, 0, sD>>>(W1a_root, W1a_rel, Wta, INA);
    cudaEventRecord(evPrepA, sD);
    prep_wT<<<dim3(HD / 32, 4), 256, 0, sD>>>(W2a_root, W2a_rel, Wt2a, HD);
    cudaEventRecord(evPrep2A, sD);

    // ---- sB: bond chain ----
    expand_bond<<<(NN * NEIGH + T - 1) / T, T, 0, sB>>>(bond);
    prep_wT<<<dim3(INB / 32, 4), 256, 0, sB>>>(W1b_root, W1b_rel, Wtb, INB);
    gemm_mma<<<ggrid, 256, SMEM_GEMM, sB>>>(Xb, Wtb, Hb, INB);
    cudaStreamWaitEvent(sB, evGraph, 0);
    gather_kernel<0><<<GGRID, 256, 0, sB>>>(Hb, b1b, bfx, nullptr);
    prep_wT<<<dim3(HD / 32, 4), 256, 0, sB>>>(W2b_root, W2b_rel, Wt2b, HD);
    gemm_mma<<<ggrid, 256, SMEM_GEMM, sB>>>(bfx, Wt2b, Hb, HD);
    gather_kernel<1><<<GGRID, 256, 0, sB>>>(Hb, b2b, nullptr, bfp);
    cudaEventRecord(evJoin, sB);

    // ---- default: angle chain (critical path) ----
    expand_angle<<<(NN * 72 + T - 1) / T, T>>>(angle);
    cudaStreamWaitEvent(0, evPrepA, 0);
    gemm_mma<<<ggrid, 256, SMEM_GEMM>>>(Xa, Wta, Ha, INA);
    cudaStreamWaitEvent(0, evGraph, 0);
    gather_kernel<0><<<GGRID, 256>>>(Ha, b1a, afx, nullptr);
    cudaStreamWaitEvent(0, evPrep2A, 0);
    gemm_mma<<<ggrid, 256, SMEM_GEMM>>>(afx, Wt2a, Ha, HD);
    gather_kernel<1><<<GGRID, 256>>>(Ha, b2a, nullptr, afp);

    // ---- join + pooling + FC ----
    cudaStreamWaitEvent(0, evJoin, 0);
    pool_kernel<<<(NN + POOL_NODES - 1) / POOL_NODES, 128>>>(crys);
    fc_kernel<<<1, 64>>>(crys, fcW, fcb, out);
}